// round 14
// baseline (speedup 1.0000x reference)
#include <cuda_runtime.h>
#include <cuda_bf16.h>
#include <cuda_fp16.h>
#include <cstdint>

#define B 4096

__device__ float g_out3[B * 288];    // conv3 out (pre-BN), [b][oc*9+pos]
__device__ float g_stats[64];
__device__ float g_Wc[3 * 288 * 10];
__device__ float g_bc[30];

// ---------------- portable tensor-core helpers (sm_80+ PTX only) ---------------
__device__ __forceinline__ uint32_t smem_u32(const void* p) {
    uint32_t a;
    asm("{ .reg .u64 t; cvta.to.shared.u64 t, %1; cvt.u32.u64 %0, t; }" : "=r"(a) : "l"(p));
    return a;
}
#define LDSM4(r, addr) \
    asm volatile("ldmatrix.sync.aligned.m8n8.x4.shared.b16 {%0,%1,%2,%3}, [%4];" \
                 : "=r"((r)[0]), "=r"((r)[1]), "=r"((r)[2]), "=r"((r)[3]) : "r"(addr))
__device__ __forceinline__ void mma16816(float* c, const uint32_t a[4], uint32_t b0, uint32_t b1) {
    asm volatile("mma.sync.aligned.m16n8k16.row.col.f32.f16.f16.f32 "
                 "{%0,%1,%2,%3}, {%4,%5,%6,%7}, {%8,%9}, {%0,%1,%2,%3};"
                 : "+f"(c[0]), "+f"(c[1]), "+f"(c[2]), "+f"(c[3])
                 : "r"(a[0]), "r"(a[1]), "r"(a[2]), "r"(a[3]), "r"(b0), "r"(b1));
}
__device__ __forceinline__ void mma_pair(float* c0, float* c1, const uint32_t a[4], const uint32_t b[4]) {
    mma16816(c0, a, b[0], b[1]);
    mma16816(c1, a, b[2], b[3]);
}
__device__ __forceinline__ void split_store(char* smem, uint32_t oh, uint32_t ol, float v) {
    __half h = __float2half_rn(v);
    __half l = __float2half_rn(v - __half2float(h));
    *(__half*)(smem + oh) = h;
    *(__half*)(smem + ol) = l;
}
#define CP_COMMIT asm volatile("cp.async.commit_group;")
#define CP_WAIT0  asm volatile("cp.async.wait_group 0;" ::: "memory")
#define CP_WAIT1  asm volatile("cp.async.wait_group 1;" ::: "memory")
#define TEAM_SYNC(team) asm volatile("bar.sync %0, 256;" :: "r"((team) + 1) : "memory")

__global__ void dummy_kernel() {}

// ---------------- fully fused conv1+conv2+conv3 ---------------------------------
#define SAS 40
#define SM_B   1024
#define SB_MAT 2560
#define A2T(team) (93184u + (uint32_t)(team) * 40960u)
#define A3T(team) (175104u + (uint32_t)(team) * 12800u)
#define XBT(team, buf) (210240u + (uint32_t)(team) * 6272u + (uint32_t)(buf) * 3136u)
#define SM_W1S 222784u
#define SM_B1S 223936u
#define SM_TOTAL 224064

__device__ __forceinline__ void prefetch_x(uint32_t sb, uint32_t xoff,
                                           const float* __restrict__ x, int img, int ttid) {
    if (ttid < 196) {
        uint32_t dst = sb + xoff + (uint32_t)ttid * 16u;
        const char* src = (const char*)(x + (size_t)img * 784) + ttid * 16;
        asm volatile("cp.async.ca.shared.global [%0], [%1], 16;" :: "r"(dst), "l"(src));
    }
}
__device__ __forceinline__ void prefetch_x7(uint32_t sb, uint32_t xoff,
                                            const float* __restrict__ x, int img, int lane) {
    for (int c = lane; c < 196; c += 32) {
        uint32_t dst = sb + xoff + (uint32_t)c * 16u;
        const char* src = (const char*)(x + (size_t)img * 784) + c * 16;
        asm volatile("cp.async.ca.shared.global [%0], [%1], 16;" :: "r"(dst), "l"(src));
    }
}

__device__ __forceinline__ void zero_pads(char* smem, uint32_t bufbase, int ttid) {
    for (int z = ttid; z < 600; z += 256) {
        int si = z / 300, r = z - si * 300;
        int ri = r / 5, q = r - ri * 5;
        int row;
        if (ri < 17) row = ri;
        else if (ri < 43) { int k = ri - 17; row = (k >> 1) * 16 + 31 + (k & 1); }
        else row = 239 + (ri - 43);
        *(float4*)(smem + bufbase + si * 20480 + row * 80 + q * 16) =
            make_float4(0.f, 0.f, 0.f, 0.f);
    }
}

// one conv1 unit: 1 pooled position x 8 output channels
__device__ void conv1_unit(char* smem, uint32_t xoff, uint32_t a2b, int u) {
    const float* xs = (const float*)(smem + xoff);
    const float* w1s = (const float*)(smem + SM_W1S);
    const float* b1s = (const float*)(smem + SM_B1S);
    int pos = u >> 2, ocg = u & 3;
    int ph = pos / 14, pw = pos - ph * 14;
    float p[4][4];
#pragma unroll
    for (int r = 0; r < 4; r++) {
        int ir = 2 * ph - 1 + r;
#pragma unroll
        for (int c = 0; c < 4; c++) {
            int icx = 2 * pw - 1 + c;
            p[r][c] = (ir >= 0 && ir < 28 && icx >= 0 && icx < 28) ? xs[ir * 28 + icx] : 0.f;
        }
    }
    uint32_t rowoff = (uint32_t)((((ph + 1) * 16) + pw + 1) * SAS) * 2;
#pragma unroll 2
    for (int o8 = 0; o8 < 8; o8++) {
        int oc = ocg * 8 + o8;
        const float* w = w1s + oc * 9;
        float a0 = 0.f, a1 = 0.f, a2 = 0.f, a3 = 0.f;
#pragma unroll
        for (int kh = 0; kh < 3; kh++)
#pragma unroll
            for (int kw = 0; kw < 3; kw++) {
                float wv = w[kh * 3 + kw];
                a0 += p[kh][kw] * wv;     a1 += p[kh][kw + 1] * wv;
                a2 += p[kh + 1][kw] * wv; a3 += p[kh + 1][kw + 1] * wv;
            }
        float v = fmaxf(fmaxf(fmaxf(a0, a1), fmaxf(a2, a3)) + b1s[oc], 0.f);
        uint32_t off = rowoff + (uint32_t)oc * 2u;
        split_store(smem, a2b + off, a2b + 20480u + off, v);
    }
}

__global__ void __launch_bounds__(512, 1) conv123_kernel(
    const float* __restrict__ x,
    const float* __restrict__ cw1, const float* __restrict__ cb1,
    const float* __restrict__ cw2, const float* __restrict__ cb2,
    const float* __restrict__ cw3, const float* __restrict__ cb3) {
    extern __shared__ char smem[];
    uint32_t sb = smem_u32(smem);
    int tid = threadIdx.x;
    int team = tid >> 8, ttid = tid & 255;
    int wid = ttid >> 5, lane = tid & 31;
    float* ssum = (float*)(smem + 64);
    float* ssq  = (float*)(smem + 192);
    uint32_t a2b = A2T(team), a3b = A3T(team);
    int first_img = blockIdx.x + 148 * team;

    if (tid < 32) { ssum[tid] = 0.f; ssq[tid] = 0.f; }
    for (int i = tid; i < 1600; i += 512)
        ((float4*)(smem + A3T(0)))[i] = make_float4(0.f, 0.f, 0.f, 0.f);
    for (int idx = tid; idx < 18432; idx += 512) {
        int conv = idx / 9216, r = idx % 9216;
        int tap = r / 1024, r2 = r % 1024;
        int oc = r2 >> 5, ic = r2 & 31;
        int kh = tap / 3, kw = tap % 3;
        float w = __ldg(&(conv ? cw3 : cw2)[oc * 288 + ic * 9 + kh * 3 + kw]);
        uint32_t bh = SM_B + (uint32_t)((conv * 9 + tap) * 2) * SB_MAT + (oc * SAS + ic) * 2;
        split_store(smem, bh, bh + SB_MAT, w);
    }
    for (int i = tid; i < 288; i += 512) ((float*)(smem + SM_W1S))[i] = cw1[i];
    if (tid < 32) ((float*)(smem + SM_B1S))[tid] = cb1[tid];
    zero_pads(smem, a2b, ttid);
    prefetch_x(sb, XBT(team, 0), x, first_img, ttid);
    CP_COMMIT;
    CP_WAIT0;
    __syncthreads();
    for (int u = ttid; u < 784; u += 256) conv1_unit(smem, XBT(team, 0), a2b, u);
    if (first_img + 296 < B) prefetch_x(sb, XBT(team, 1), x, first_img + 296, ttid);
    CP_COMMIT;
    CP_WAIT0;
    TEAM_SYNC(team);

    int g = lane >> 2, tg = lane & 3;
    uint32_t a_r = (uint32_t)(lane & 15), a_c = (uint32_t)((lane >> 4) * 8);
    uint32_t b_row = (uint32_t)(((lane >> 4) << 3) + (lane & 7));
    uint32_t b_c = (uint32_t)((lane & 8) ? 8 : 0);
    int mt[2] = { 2 * wid + 1, 2 * wid + 2 };
    int cv2 = wid < 7;
    int tnum = wid >> 1, np3 = wid & 1;
    int keep = ((g & 1) == 0) && (g < 6);
    float bias0[4], bias1[4];
#pragma unroll
    for (int n = 0; n < 4; n++) {
        bias0[n] = __ldg(&cb2[n * 8 + 2 * tg]);
        bias1[n] = __ldg(&cb2[n * 8 + 2 * tg + 1]);
    }
    float bnsum[2][2] = {{0.f, 0.f}, {0.f, 0.f}};
    float bnsq[2][2]  = {{0.f, 0.f}, {0.f, 0.f}};

    for (int it = 0; it < 14; it++) {
        int img = first_img + 296 * it;
        int active = img < B;
        // ---- P1: conv2 (warps 0-6); warp 7: x-prefetch duty ----
        if (cv2) {
            float acc[2][4][4];
#pragma unroll
            for (int t = 0; t < 2; t++)
#pragma unroll
                for (int n = 0; n < 4; n++)
#pragma unroll
                    for (int i = 0; i < 4; i++) acc[t][n][i] = 0.f;
#pragma unroll
            for (int tap = 0; tap < 9; tap++) {
                uint32_t bmat = sb + SM_B + (uint32_t)(tap * 2) * SB_MAT;
                uint32_t Bh[2][2][4], Bl[2][2][4];
#pragma unroll
                for (int np = 0; np < 2; np++)
#pragma unroll
                    for (int j = 0; j < 2; j++) {
                        uint32_t boff = (((uint32_t)np * 16 + b_row) * SAS + (uint32_t)j * 16 + b_c) * 2;
                        LDSM4(Bh[np][j], bmat + boff);
                        LDSM4(Bl[np][j], bmat + SB_MAT + boff);
                    }
                int dr = (tap / 3 - 1) * 16 + (tap % 3 - 1) + 1;
#pragma unroll
                for (int j = 0; j < 2; j++) {
                    uint32_t Ah[2][4], Al[2][4];
#pragma unroll
                    for (int t = 0; t < 2; t++) {
                        uint32_t aoff = (uint32_t)((mt[t] * 16 + dr + (int)a_r) * SAS) * 2
                                        + ((uint32_t)j * 16 + a_c) * 2;
                        LDSM4(Ah[t], sb + a2b + aoff);
                        LDSM4(Al[t], sb + a2b + 20480u + aoff);
                    }
#pragma unroll
                    for (int t = 0; t < 2; t++) {
                        mma_pair(acc[t][0], acc[t][1], Ah[t], Bh[0][j]);
                        mma_pair(acc[t][2], acc[t][3], Ah[t], Bh[1][j]);
                    }
#pragma unroll
                    for (int t = 0; t < 2; t++) {
                        mma_pair(acc[t][0], acc[t][1], Ah[t], Bl[0][j]);
                        mma_pair(acc[t][2], acc[t][3], Ah[t], Bl[1][j]);
                    }
#pragma unroll
                    for (int t = 0; t < 2; t++) {
                        mma_pair(acc[t][0], acc[t][1], Al[t], Bh[0][j]);
                        mma_pair(acc[t][2], acc[t][3], Al[t], Bh[1][j]);
                    }
                }
            }
            // in-register conv2 pool -> A3
#pragma unroll
            for (int n = 0; n < 4; n++) {
                float vA0 = fmaxf(acc[0][n][0], acc[1][n][0]);
                float vA1 = fmaxf(acc[0][n][1], acc[1][n][1]);
                float vB0 = fmaxf(acc[0][n][2], acc[1][n][2]);
                float vB1 = fmaxf(acc[0][n][3], acc[1][n][3]);
                float qA0 = fmaxf(vA0, __shfl_xor_sync(0xffffffffu, vA0, 4));
                float qA1 = fmaxf(vA1, __shfl_xor_sync(0xffffffffu, vA1, 4));
                float qB0 = fmaxf(vB0, __shfl_xor_sync(0xffffffffu, vB0, 4));
                float qB1 = fmaxf(vB1, __shfl_xor_sync(0xffffffffu, vB1, 4));
                if ((g & 1) == 0) {
                    int oc0 = n * 8 + 2 * tg;
                    int pcA = g >> 1;
                    uint32_t rowA = (uint32_t)((wid + 2) * 8 + pcA);
                    uint32_t offA = (rowA * SAS + (uint32_t)oc0) * 2;
                    split_store(smem, a3b + offA, a3b + 6400u + offA,
                                fmaxf(qA0 + bias0[n], 0.f));
                    split_store(smem, a3b + offA + 2, a3b + 6400u + offA + 2,
                                fmaxf(qA1 + bias1[n], 0.f));
                    int pcB = (g >> 1) + 4;
                    if (pcB < 7) {
                        uint32_t rowB = (uint32_t)((wid + 2) * 8 + pcB);
                        uint32_t offB = (rowB * SAS + (uint32_t)oc0) * 2;
                        split_store(smem, a3b + offB, a3b + 6400u + offB,
                                    fmaxf(qB0 + bias0[n], 0.f));
                        split_store(smem, a3b + offB + 2, a3b + 6400u + offB + 2,
                                    fmaxf(qB1 + bias1[n], 0.f));
                    }
                }
            }
        } else {
            // warp 7: drain previous x group, issue prefetch for it+2
            CP_WAIT0;
            int imgP = img + 592;
            if (it < 12 && imgP < B)
                prefetch_x7(sb, XBT(team, it & 1), x, imgP, lane);
            CP_COMMIT;
        }
        TEAM_SYNC(team);                         // S_a: A3 ready, A2 free, x visible
        // ---- P2': conv3 (warps 0-5) + conv1(next img, all warps) ----
        int imgN = img + 296;
        uint32_t xoff = XBT(team, (it + 1) & 1);
        if (wid < 6) {
            float acc3[2][2][4];
#pragma unroll
            for (int bk = 0; bk < 2; bk++)
#pragma unroll
                for (int n = 0; n < 2; n++)
#pragma unroll
                    for (int i = 0; i < 4; i++) acc3[bk][n][i] = 0.f;
            int base = 16 + tnum * 16;
#pragma unroll
            for (int tap = 0; tap < 9; tap++) {
                uint32_t bmat = sb + SM_B + (uint32_t)(18 + tap * 2) * SB_MAT;
                uint32_t B3h[2][4], B3l[2][4];
#pragma unroll
                for (int j = 0; j < 2; j++) {
                    uint32_t boff = (((uint32_t)np3 * 16 + b_row) * SAS + (uint32_t)j * 16 + b_c) * 2;
                    LDSM4(B3h[j], bmat + boff);
                    LDSM4(B3l[j], bmat + SB_MAT + boff);
                }
                int dr3 = (tap / 3 - 1) * 8 + (tap % 3 - 1);
#pragma unroll
                for (int j = 0; j < 2; j++) {
                    uint32_t aoff = (uint32_t)((base + dr3 + (int)a_r) * SAS) * 2
                                    + ((uint32_t)j * 16 + a_c) * 2;
                    uint32_t A3h[4], A3l[4];
                    LDSM4(A3h, sb + a3b + aoff);
                    LDSM4(A3l, sb + a3b + 6400u + aoff);
                    mma_pair(acc3[j][0], acc3[j][1], A3h, B3h[j]);
                    mma_pair(acc3[j ^ 1][0], acc3[j ^ 1][1], A3h, B3l[j]);
                    mma_pair(acc3[j][0], acc3[j][1], A3l, B3h[j]);
                }
            }
            // in-register conv3 pool -> g_out3 + BN partials
            float* go = g_out3 + (size_t)img * 288;
#pragma unroll
            for (int n = 0; n < 2; n++) {
                float r0 = acc3[0][n][0] + acc3[1][n][0];   // row 2tnum,   col oc0
                float r1 = acc3[0][n][1] + acc3[1][n][1];   // row 2tnum,   col oc0+1
                float r2 = acc3[0][n][2] + acc3[1][n][2];   // row 2tnum+1, col oc0
                float r3 = acc3[0][n][3] + acc3[1][n][3];
                float m0 = fmaxf(r0, r2);
                float m1 = fmaxf(r1, r3);
                float p0 = fmaxf(m0, __shfl_xor_sync(0xffffffffu, m0, 4));
                float p1 = fmaxf(m1, __shfl_xor_sync(0xffffffffu, m1, 4));
                if (keep && active) {
                    int oc0 = np3 * 16 + n * 8 + 2 * tg;
                    int pos = tnum * 3 + (g >> 1);
                    float v0 = fmaxf(p0 + __ldg(&cb3[oc0]), 0.f);
                    float v1 = fmaxf(p1 + __ldg(&cb3[oc0 + 1]), 0.f);
                    go[oc0 * 9 + pos] = v0;
                    go[(oc0 + 1) * 9 + pos] = v1;
                    bnsum[n][0] += v0; bnsq[n][0] += v0 * v0;
                    bnsum[n][1] += v1; bnsq[n][1] += v1 * v1;
                }
            }
            if (imgN < B) {
                for (int k = 0; k < 2; k++)
                    conv1_unit(smem, xoff, a2b, ttid + 192 * k);
            }
        } else {
            if (imgN < B) {
                int t = ttid - 192;
                for (int k = 0; k < 7; k++) {
                    int u = 384 + t + 64 * k;
                    if (u < 784) conv1_unit(smem, xoff, a2b, u);
                }
            }
        }
        TEAM_SYNC(team);                         // S_c: A2 rebuilt
    }
    // BN partial flush
    if (wid < 6 && keep) {
        int ocb = np3 * 16 + 2 * tg;
#pragma unroll
        for (int n = 0; n < 2; n++) {
            atomicAdd(&ssum[ocb + n * 8], bnsum[n][0]);
            atomicAdd(&ssq[ocb + n * 8], bnsq[n][0]);
            atomicAdd(&ssum[ocb + n * 8 + 1], bnsum[n][1]);
            atomicAdd(&ssq[ocb + n * 8 + 1], bnsq[n][1]);
        }
    }
    __syncthreads();
    if (tid < 32) {
        atomicAdd(&g_stats[tid], ssum[tid]);
        atomicAdd(&g_stats[32 + tid], ssq[tid]);
    }
}

// ---------------- compose expert chain: 24 blocks (3 actions x 8 slices) --------
__global__ void __launch_bounds__(128) compose_kernel(
    const float* __restrict__ ew1, const float* __restrict__ eb1,
    const float* __restrict__ ew2, const float* __restrict__ eb2,
    const float* __restrict__ ew3, const float* __restrict__ eb3) {
    __shared__ float E3s[1280];
    __shared__ float C1s[1280];
    int tid = threadIdx.x;
    int a = blockIdx.x >> 3, s = blockIdx.x & 7;
    if (blockIdx.x == 0 && tid < 64) g_stats[tid] = 0.f;
    for (int i = tid; i < 1280; i += 128) E3s[i] = ew3[a * 1280 + i];
    __syncthreads();
    {
        float sc[10];
#pragma unroll
        for (int o = 0; o < 10; o++) sc[o] = 0.f;
        const float* e2r = ew2 + a * 16384 + tid * 128;
#pragma unroll 4
        for (int j = 0; j < 128; j++) {
            float e = e2r[j];
#pragma unroll
            for (int o = 0; o < 10; o++) sc[o] += e * E3s[j * 10 + o];
        }
#pragma unroll
        for (int o = 0; o < 10; o++) C1s[tid * 10 + o] = sc[o];
    }
    __syncthreads();
    if (s == 0 && tid < 10) {
        float bb = eb3[a * 10 + tid];
        for (int i = 0; i < 128; i++) {
            bb += eb2[a * 128 + i] * E3s[i * 10 + tid];
            bb += eb1[a * 128 + i] * C1s[i * 10 + tid];
        }
        g_bc[a * 10 + tid] = bb;
    }
    if (tid < 36) {
        int k = s * 36 + tid;
        float sc[10];
#pragma unroll
        for (int o = 0; o < 10; o++) sc[o] = 0.f;
        const float* e1r = ew1 + a * 36864 + k * 128;
#pragma unroll 4
        for (int i = 0; i < 128; i++) {
            float e = e1r[i];
#pragma unroll
            for (int o = 0; o < 10; o++) sc[o] += e * C1s[i * 10 + o];
        }
#pragma unroll
        for (int o = 0; o < 10; o++) g_Wc[(a * 288 + k) * 10 + o] = sc[o];
    }
}

// ---------------- MLP: smem-staged weights, double-buffered cp.async ------------
#define MS_SCALE 0
#define MS_YS    256
#define MS_HA    18688
#define MS_HB    26880
#define MS_WBUF  35072
#define MLP_SMEM 67840

__device__ __forceinline__ void mlp_prefetch(uint32_t sb, int ti,
                                             const float* __restrict__ pw1,
                                             const float* __restrict__ pw2, int tid) {
    const char* src = (const char*)((ti < 9) ? (pw1 + ti * 4096) : (pw2 + (ti - 9) * 4096));
    uint32_t dst = sb + MS_WBUF + (uint32_t)(ti & 1) * 16384u;
#pragma unroll
    for (int c = 0; c < 4; c++) {
        int i = tid + c * 256;
        asm volatile("cp.async.ca.shared.global [%0], [%1], 16;"
                     :: "r"(dst + (uint32_t)i * 16u), "l"(src + i * 16) : "memory");
    }
}

__global__ void __launch_bounds__(256) mlp_kernel(
    const float* __restrict__ pw1, const float* __restrict__ pb1,
    const float* __restrict__ pw2, const float* __restrict__ pb2,
    const float* __restrict__ pw3, const float* __restrict__ pb3,
    const float* __restrict__ bn_g, const float* __restrict__ bn_b,
    float* __restrict__ out, int write_actions) {
    extern __shared__ char ms[];
    uint32_t sb = smem_u32(ms);
    float* s_scale = (float*)(ms + MS_SCALE);
    float* s_shift = s_scale + 32;
    float* ys = (float*)(ms + MS_YS);
    float* ha = (float*)(ms + MS_HA);
    float* hb = (float*)(ms + MS_HB);
    int tid = threadIdx.x;
    int w = tid >> 5, lane = tid & 31;
    int e0 = blockIdx.x * 16;

    mlp_prefetch(sb, 0, pw1, pw2, tid); CP_COMMIT;
    mlp_prefetch(sb, 1, pw1, pw2, tid); CP_COMMIT;

    if (tid < 32) {
        const float inv_n = 1.0f / (float)(B * 9);
        float m = g_stats[tid] * inv_n;
        float var = g_stats[32 + tid] * inv_n - m * m;
        float sc = bn_g[tid] * rsqrtf(var + 1e-5f);
        s_scale[tid] = sc;
        s_shift[tid] = bn_b[tid] - m * sc;
    }
    __syncthreads();
    for (int idx = tid; idx < 4608; idx += 256) {
        int e = idx / 288, k = idx - e * 288, c = k / 9;
        ys[idx] = g_out3[(e0 + e) * 288 + k] * s_scale[c] + s_shift[c];
    }

    const float* y0p = ys + (2 * w) * 288;
    const float* y1p = ys + (2 * w + 1) * 288;
    float acc1[2][4], acc2[2][4];
    {
        float4 bv = *(const float4*)(pb1 + lane * 4);
        acc1[0][0] = bv.x; acc1[0][1] = bv.y; acc1[0][2] = bv.z; acc1[0][3] = bv.w;
        acc1[1][0] = bv.x; acc1[1][1] = bv.y; acc1[1][2] = bv.z; acc1[1][3] = bv.w;
        float4 bv2 = *(const float4*)(pb2 + lane * 4);
        acc2[0][0] = bv2.x; acc2[0][1] = bv2.y; acc2[0][2] = bv2.z; acc2[0][3] = bv2.w;
        acc2[1][0] = bv2.x; acc2[1][1] = bv2.y; acc2[1][2] = bv2.z; acc2[1][3] = bv2.w;
    }

    for (int ti = 0; ti < 13; ti++) {
        if (ti < 12) { CP_WAIT1; } else { CP_WAIT0; }
        __syncthreads();
        const float4* wt = (const float4*)(ms + MS_WBUF + (uint32_t)(ti & 1) * 16384u);
        if (ti < 9) {
            int kb = ti * 32;
#pragma unroll 8
            for (int kl = 0; kl < 32; kl++) {
                float4 w4 = wt[kl * 32 + lane];
                float y0 = y0p[kb + kl], y1 = y1p[kb + kl];
                acc1[0][0] += y0 * w4.x; acc1[0][1] += y0 * w4.y;
                acc1[0][2] += y0 * w4.z; acc1[0][3] += y0 * w4.w;
                acc1[1][0] += y1 * w4.x; acc1[1][1] += y1 * w4.y;
                acc1[1][2] += y1 * w4.z; acc1[1][3] += y1 * w4.w;
            }
            if (ti == 8) {
#pragma unroll
                for (int e = 0; e < 2; e++)
                    *(float4*)(ha + (2 * w + e) * 128 + lane * 4) =
                        make_float4(fmaxf(acc1[e][0], 0.f), fmaxf(acc1[e][1], 0.f),
                                    fmaxf(acc1[e][2], 0.f), fmaxf(acc1[e][3], 0.f));
            }
        } else {
            int kb = (ti - 9) * 32;
            const float* h0 = ha + (2 * w) * 128;
            const float* h1 = ha + (2 * w + 1) * 128;
#pragma unroll 8
            for (int kl = 0; kl < 32; kl++) {
                float4 w4 = wt[kl * 32 + lane];
                float y0 = h0[kb + kl], y1 = h1[kb + kl];
                acc2[0][0] += y0 * w4.x; acc2[0][1] += y0 * w4.y;
                acc2[0][2] += y0 * w4.z; acc2[0][3] += y0 * w4.w;
                acc2[1][0] += y1 * w4.x; acc2[1][1] += y1 * w4.y;
                acc2[1][2] += y1 * w4.z; acc2[1][3] += y1 * w4.w;
            }
        }
        __syncthreads();
        if (ti + 2 < 13) { mlp_prefetch(sb, ti + 2, pw1, pw2, tid); CP_COMMIT; }
    }
#pragma unroll
    for (int e = 0; e < 2; e++)
        *(float4*)(hb + (2 * w + e) * 128 + lane * 4) =
            make_float4(fmaxf(acc2[e][0], 0.f), fmaxf(acc2[e][1], 0.f),
                        fmaxf(acc2[e][2], 0.f), fmaxf(acc2[e][3], 0.f));
    __syncwarp();

    for (int e = 0; e < 2; e++) {
        int le = 2 * w + e;
        float p0 = 0.f, p1 = 0.f, p2 = 0.f;
#pragma unroll
        for (int kk = 0; kk < 4; kk++) {
            int k = lane + 32 * kk;
            float hv = hb[le * 128 + k];
            const float* wr = pw3 + k * 3;
            p0 += hv * wr[0]; p1 += hv * wr[1]; p2 += hv * wr[2];
        }
#pragma unroll
        for (int off = 16; off > 0; off >>= 1) {
            p0 += __shfl_down_sync(0xffffffffu, p0, off);
            p1 += __shfl_down_sync(0xffffffffu, p1, off);
            p2 += __shfl_down_sync(0xffffffffu, p2, off);
        }
        int a = 0;
        if (lane == 0) {
            p0 += __ldg(&pb3[0]); p1 += __ldg(&pb3[1]); p2 += __ldg(&pb3[2]);
            float best = p0;
            if (p1 > best) { best = p1; a = 1; }
            if (p2 > best) { a = 2; }
        }
        a = __shfl_sync(0xffffffffu, a, 0);
        float po[10];
#pragma unroll
        for (int o = 0; o < 10; o++) po[o] = 0.f;
        const float* Wb = g_Wc + a * 2880;
        const float* ye = ys + le * 288;
#pragma unroll
        for (int kk = 0; kk < 9; kk++) {
            int k = lane + 32 * kk;
            float yv = ye[k];
            const float* wr = Wb + k * 10;
#pragma unroll
            for (int o = 0; o < 10; o++) po[o] += yv * wr[o];
        }
#pragma unroll
        for (int off = 16; off > 0; off >>= 1) {
#pragma unroll
            for (int o = 0; o < 10; o++) po[o] += __shfl_down_sync(0xffffffffu, po[o], off);
        }
        if (lane == 0) {
            int gg = e0 + le;
#pragma unroll
            for (int o = 0; o < 10; o++) out[gg * 10 + o] = po[o] + g_bc[a * 10 + o];
            if (write_actions) out[B * 10 + gg] = (float)a;
        }
    }
}

// ---------------- launch --------------------------------------------------------
extern "C" void kernel_launch(void* const* d_in, const int* in_sizes, int n_in,
                              void* d_out, int out_size) {
    const float* x    = (const float*)d_in[0];
    const float* cw1  = (const float*)d_in[1];
    const float* cb1  = (const float*)d_in[2];
    const float* cw2  = (const float*)d_in[3];
    const float* cb2  = (const float*)d_in[4];
    const float* cw3  = (const float*)d_in[5];
    const float* cb3  = (const float*)d_in[6];
    const float* bn_g = (const float*)d_in[7];
    const float* bn_b = (const float*)d_in[8];
    const float* pw1  = (const float*)d_in[9];
    const float* pb1  = (const float*)d_in[10];
    const float* pw2  = (const float*)d_in[11];
    const float* pb2  = (const float*)d_in[12];
    const float* pw3  = (const float*)d_in[13];
    const float* pb3  = (const float*)d_in[14];
    const float* ew1  = (const float*)d_in[15];
    const float* eb1  = (const float*)d_in[16];
    const float* ew2  = (const float*)d_in[17];
    const float* eb2  = (const float*)d_in[18];
    const float* ew3  = (const float*)d_in[19];
    const float* eb3  = (const float*)d_in[20];
    float* out = (float*)d_out;
    int write_actions = (out_size >= B * 10 + B) ? 1 : 0;

    cudaFuncSetAttribute(conv123_kernel, cudaFuncAttributeMaxDynamicSharedMemorySize, SM_TOTAL);
    cudaFuncSetAttribute(mlp_kernel, cudaFuncAttributeMaxDynamicSharedMemorySize, MLP_SMEM);

    compose_kernel<<<24, 128>>>(ew1, eb1, ew2, eb2, ew3, eb3);                // 1 (also zeroes g_stats)
    dummy_kernel<<<1, 32>>>();                                                // 2
    dummy_kernel<<<1, 32>>>();                                                // 3
    conv123_kernel<<<148, 512, SM_TOTAL>>>(x, cw1, cb1, cw2, cb2, cw3, cb3);  // 4 -> profiled
    mlp_kernel<<<B / 16, 256, MLP_SMEM>>>(pw1, pb1, pw2, pb2, pw3, pb3,
                                          bn_g, bn_b, out, write_actions);    // 5
}

// round 15
// speedup vs baseline: 1.0141x; 1.0141x over previous
#include <cuda_runtime.h>
#include <cuda_bf16.h>
#include <cuda_fp16.h>
#include <cstdint>

#define B 4096

__device__ float g_out3[B * 288];    // conv3 out (pre-BN), [b][oc*9+pos]
__device__ float g_stats[64];
__device__ float g_Wc[3 * 288 * 10];
__device__ float g_bc[30];

// ---------------- portable tensor-core helpers (sm_80+ PTX only) ---------------
__device__ __forceinline__ uint32_t smem_u32(const void* p) {
    uint32_t a;
    asm("{ .reg .u64 t; cvta.to.shared.u64 t, %1; cvt.u32.u64 %0, t; }" : "=r"(a) : "l"(p));
    return a;
}
#define LDSM4(r, addr) \
    asm volatile("ldmatrix.sync.aligned.m8n8.x4.shared.b16 {%0,%1,%2,%3}, [%4];" \
                 : "=r"((r)[0]), "=r"((r)[1]), "=r"((r)[2]), "=r"((r)[3]) : "r"(addr))
__device__ __forceinline__ void mma16816(float* c, const uint32_t a[4], uint32_t b0, uint32_t b1) {
    asm volatile("mma.sync.aligned.m16n8k16.row.col.f32.f16.f16.f32 "
                 "{%0,%1,%2,%3}, {%4,%5,%6,%7}, {%8,%9}, {%0,%1,%2,%3};"
                 : "+f"(c[0]), "+f"(c[1]), "+f"(c[2]), "+f"(c[3])
                 : "r"(a[0]), "r"(a[1]), "r"(a[2]), "r"(a[3]), "r"(b0), "r"(b1));
}
__device__ __forceinline__ void mma_pair(float* c0, float* c1, const uint32_t a[4], const uint32_t b[4]) {
    mma16816(c0, a, b[0], b[1]);
    mma16816(c1, a, b[2], b[3]);
}
__device__ __forceinline__ void split_store(char* smem, uint32_t oh, uint32_t ol, float v) {
    __half h = __float2half_rn(v);
    __half l = __float2half_rn(v - __half2float(h));
    *(__half*)(smem + oh) = h;
    *(__half*)(smem + ol) = l;
}
#define CP_COMMIT asm volatile("cp.async.commit_group;")
#define CP_WAIT0  asm volatile("cp.async.wait_group 0;" ::: "memory")
#define CP_WAIT1  asm volatile("cp.async.wait_group 1;" ::: "memory")
#define TEAM_SYNC(team) asm volatile("bar.sync %0, 256;" :: "r"((team) + 1) : "memory")

// ---------------- fully fused conv1+conv2+conv3 (R13 known-good) ----------------
#define SAS 40
#define SM_B   1024
#define SB_MAT 2560
#define A2T(team) (93184u + (uint32_t)(team) * 40960u)
#define A3T(team) (175104u + (uint32_t)(team) * 12800u)
#define C3T(team) (200704u + (uint32_t)(team) * 4752u)
#define XBT(team, buf) (210240u + (uint32_t)(team) * 6272u + (uint32_t)(buf) * 3136u)
#define SM_W1S 222784u
#define SM_B1S 223936u
#define SM_TOTAL 224064

__device__ __forceinline__ void prefetch_x(uint32_t sb, uint32_t xoff,
                                           const float* __restrict__ x, int img, int ttid) {
    if (ttid < 196) {
        uint32_t dst = sb + xoff + (uint32_t)ttid * 16u;
        const char* src = (const char*)(x + (size_t)img * 784) + ttid * 16;
        asm volatile("cp.async.ca.shared.global [%0], [%1], 16;" :: "r"(dst), "l"(src));
    }
}

__device__ __forceinline__ void zero_pads(char* smem, uint32_t bufbase, int ttid) {
    for (int z = ttid; z < 600; z += 256) {
        int si = z / 300, r = z - si * 300;
        int ri = r / 5, q = r - ri * 5;
        int row;
        if (ri < 17) row = ri;
        else if (ri < 43) { int k = ri - 17; row = (k >> 1) * 16 + 31 + (k & 1); }
        else row = 239 + (ri - 43);
        *(float4*)(smem + bufbase + si * 20480 + row * 80 + q * 16) =
            make_float4(0.f, 0.f, 0.f, 0.f);
    }
}

__device__ void conv1_compute(char* smem, uint32_t xoff, uint32_t a2b, int ttid) {
    const float* xs = (const float*)(smem + xoff);
    const float* w1s = (const float*)(smem + SM_W1S);
    const float* b1s = (const float*)(smem + SM_B1S);
    for (int u = ttid; u < 784; u += 256) {
        int pos = u >> 2, ocg = u & 3;
        int ph = pos / 14, pw = pos - ph * 14;
        float p[4][4];
#pragma unroll
        for (int r = 0; r < 4; r++) {
            int ir = 2 * ph - 1 + r;
#pragma unroll
            for (int c = 0; c < 4; c++) {
                int icx = 2 * pw - 1 + c;
                p[r][c] = (ir >= 0 && ir < 28 && icx >= 0 && icx < 28) ? xs[ir * 28 + icx] : 0.f;
            }
        }
        uint32_t rowoff = (uint32_t)((((ph + 1) * 16) + pw + 1) * SAS) * 2;
#pragma unroll 2
        for (int o8 = 0; o8 < 8; o8++) {
            int oc = ocg * 8 + o8;
            const float* w = w1s + oc * 9;
            float a0 = 0.f, a1 = 0.f, a2 = 0.f, a3 = 0.f;
#pragma unroll
            for (int kh = 0; kh < 3; kh++)
#pragma unroll
                for (int kw = 0; kw < 3; kw++) {
                    float wv = w[kh * 3 + kw];
                    a0 += p[kh][kw] * wv;     a1 += p[kh][kw + 1] * wv;
                    a2 += p[kh + 1][kw] * wv; a3 += p[kh + 1][kw + 1] * wv;
                }
            float v = fmaxf(fmaxf(fmaxf(a0, a1), fmaxf(a2, a3)) + b1s[oc], 0.f);
            uint32_t off = rowoff + (uint32_t)oc * 2u;
            split_store(smem, a2b + off, a2b + 20480u + off, v);
        }
    }
}

__global__ void __launch_bounds__(512, 1) conv123_kernel(
    const float* __restrict__ x,
    const float* __restrict__ cw1, const float* __restrict__ cb1,
    const float* __restrict__ cw2, const float* __restrict__ cb2,
    const float* __restrict__ cw3, const float* __restrict__ cb3) {
    extern __shared__ char smem[];
    uint32_t sb = smem_u32(smem);
    int tid = threadIdx.x;
    int team = tid >> 8, ttid = tid & 255;
    int wid = ttid >> 5, lane = tid & 31;
    float* ssum = (float*)(smem + 64);
    float* ssq  = (float*)(smem + 192);
    uint32_t a2b = A2T(team), a3b = A3T(team), c3b = C3T(team);
    float* C3 = (float*)(smem + c3b);
    int first_img = blockIdx.x + 148 * team;

    if (tid < 32) { ssum[tid] = 0.f; ssq[tid] = 0.f; }
    for (int i = tid; i < 1600; i += 512)
        ((float4*)(smem + A3T(0)))[i] = make_float4(0.f, 0.f, 0.f, 0.f);
    for (int idx = tid; idx < 18432; idx += 512) {
        int conv = idx / 9216, r = idx % 9216;
        int tap = r / 1024, r2 = r % 1024;
        int oc = r2 >> 5, ic = r2 & 31;
        int kh = tap / 3, kw = tap % 3;
        float w = __ldg(&(conv ? cw3 : cw2)[oc * 288 + ic * 9 + kh * 3 + kw]);
        uint32_t bh = SM_B + (uint32_t)((conv * 9 + tap) * 2) * SB_MAT + (oc * SAS + ic) * 2;
        split_store(smem, bh, bh + SB_MAT, w);
    }
    for (int i = tid; i < 288; i += 512) ((float*)(smem + SM_W1S))[i] = cw1[i];
    if (tid < 32) ((float*)(smem + SM_B1S))[tid] = cb1[tid];
    zero_pads(smem, a2b, ttid);
    prefetch_x(sb, XBT(team, 0), x, first_img, ttid);
    CP_COMMIT;
    CP_WAIT0;
    __syncthreads();
    conv1_compute(smem, XBT(team, 0), a2b, ttid);
    if (first_img + 296 < B) prefetch_x(sb, XBT(team, 1), x, first_img + 296, ttid);
    CP_COMMIT;
    TEAM_SYNC(team);

    int g = lane >> 2, tg = lane & 3;
    uint32_t a_r = (uint32_t)(lane & 15), a_c = (uint32_t)((lane >> 4) * 8);
    uint32_t b_row = (uint32_t)(((lane >> 4) << 3) + (lane & 7));
    uint32_t b_c = (uint32_t)((lane & 8) ? 8 : 0);
    float lsum = 0.f, lsq = 0.f, lsum2 = 0.f, lsq2 = 0.f;
    int myoc = ttid / 9, myoc2 = (ttid + 256) / 9;
    int mt[2] = { 2 * wid + 1, 2 * wid + 2 };
    int cv2 = wid < 7;
    int tnum = wid >> 1, np3 = wid & 1;
    float bias0[4], bias1[4];
#pragma unroll
    for (int n = 0; n < 4; n++) {
        bias0[n] = __ldg(&cb2[n * 8 + 2 * tg]);
        bias1[n] = __ldg(&cb2[n * 8 + 2 * tg + 1]);
    }

    for (int it = 0; it < 14; it++) {
        int img = first_img + 296 * it;
        int active = img < B;
        if (cv2) {
            float acc[2][4][4];
#pragma unroll
            for (int t = 0; t < 2; t++)
#pragma unroll
                for (int n = 0; n < 4; n++)
#pragma unroll
                    for (int i = 0; i < 4; i++) acc[t][n][i] = 0.f;
#pragma unroll
            for (int tap = 0; tap < 9; tap++) {
                uint32_t bmat = sb + SM_B + (uint32_t)(tap * 2) * SB_MAT;
                uint32_t Bh[2][2][4], Bl[2][2][4];
#pragma unroll
                for (int np = 0; np < 2; np++)
#pragma unroll
                    for (int j = 0; j < 2; j++) {
                        uint32_t boff = (((uint32_t)np * 16 + b_row) * SAS + (uint32_t)j * 16 + b_c) * 2;
                        LDSM4(Bh[np][j], bmat + boff);
                        LDSM4(Bl[np][j], bmat + SB_MAT + boff);
                    }
                int dr = (tap / 3 - 1) * 16 + (tap % 3 - 1) + 1;
#pragma unroll
                for (int j = 0; j < 2; j++) {
                    uint32_t Ah[2][4], Al[2][4];
#pragma unroll
                    for (int t = 0; t < 2; t++) {
                        uint32_t aoff = (uint32_t)((mt[t] * 16 + dr + (int)a_r) * SAS) * 2
                                        + ((uint32_t)j * 16 + a_c) * 2;
                        LDSM4(Ah[t], sb + a2b + aoff);
                        LDSM4(Al[t], sb + a2b + 20480u + aoff);
                    }
#pragma unroll
                    for (int t = 0; t < 2; t++) {
                        mma_pair(acc[t][0], acc[t][1], Ah[t], Bh[0][j]);
                        mma_pair(acc[t][2], acc[t][3], Ah[t], Bh[1][j]);
                    }
#pragma unroll
                    for (int t = 0; t < 2; t++) {
                        mma_pair(acc[t][0], acc[t][1], Ah[t], Bl[0][j]);
                        mma_pair(acc[t][2], acc[t][3], Ah[t], Bl[1][j]);
                    }
#pragma unroll
                    for (int t = 0; t < 2; t++) {
                        mma_pair(acc[t][0], acc[t][1], Al[t], Bh[0][j]);
                        mma_pair(acc[t][2], acc[t][3], Al[t], Bh[1][j]);
                    }
                }
            }
#pragma unroll
            for (int n = 0; n < 4; n++) {
                float vA0 = fmaxf(acc[0][n][0], acc[1][n][0]);
                float vA1 = fmaxf(acc[0][n][1], acc[1][n][1]);
                float vB0 = fmaxf(acc[0][n][2], acc[1][n][2]);
                float vB1 = fmaxf(acc[0][n][3], acc[1][n][3]);
                float qA0 = fmaxf(vA0, __shfl_xor_sync(0xffffffffu, vA0, 4));
                float qA1 = fmaxf(vA1, __shfl_xor_sync(0xffffffffu, vA1, 4));
                float qB0 = fmaxf(vB0, __shfl_xor_sync(0xffffffffu, vB0, 4));
                float qB1 = fmaxf(vB1, __shfl_xor_sync(0xffffffffu, vB1, 4));
                if ((g & 1) == 0) {
                    int oc0 = n * 8 + 2 * tg;
                    int pcA = g >> 1;
                    uint32_t rowA = (uint32_t)((wid + 2) * 8 + pcA);
                    uint32_t offA = (rowA * SAS + (uint32_t)oc0) * 2;
                    split_store(smem, a3b + offA, a3b + 6400u + offA,
                                fmaxf(qA0 + bias0[n], 0.f));
                    split_store(smem, a3b + offA + 2, a3b + 6400u + offA + 2,
                                fmaxf(qA1 + bias1[n], 0.f));
                    int pcB = (g >> 1) + 4;
                    if (pcB < 7) {
                        uint32_t rowB = (uint32_t)((wid + 2) * 8 + pcB);
                        uint32_t offB = (rowB * SAS + (uint32_t)oc0) * 2;
                        split_store(smem, a3b + offB, a3b + 6400u + offB,
                                    fmaxf(qB0 + bias0[n], 0.f));
                        split_store(smem, a3b + offB + 2, a3b + 6400u + offB + 2,
                                    fmaxf(qB1 + bias1[n], 0.f));
                    }
                }
            }
        }
        TEAM_SYNC(team);
        if (wid < 6) {
            float acc3[2][2][4];
#pragma unroll
            for (int bk = 0; bk < 2; bk++)
#pragma unroll
                for (int n = 0; n < 2; n++)
#pragma unroll
                    for (int i = 0; i < 4; i++) acc3[bk][n][i] = 0.f;
            int base = 16 + tnum * 16;
#pragma unroll
            for (int tap = 0; tap < 9; tap++) {
                uint32_t bmat = sb + SM_B + (uint32_t)(18 + tap * 2) * SB_MAT;
                uint32_t B3h[2][4], B3l[2][4];
#pragma unroll
                for (int j = 0; j < 2; j++) {
                    uint32_t boff = (((uint32_t)np3 * 16 + b_row) * SAS + (uint32_t)j * 16 + b_c) * 2;
                    LDSM4(B3h[j], bmat + boff);
                    LDSM4(B3l[j], bmat + SB_MAT + boff);
                }
                int dr3 = (tap / 3 - 1) * 8 + (tap % 3 - 1);
#pragma unroll
                for (int j = 0; j < 2; j++) {
                    uint32_t aoff = (uint32_t)((base + dr3 + (int)a_r) * SAS) * 2
                                    + ((uint32_t)j * 16 + a_c) * 2;
                    uint32_t A3h[4], A3l[4];
                    LDSM4(A3h, sb + a3b + aoff);
                    LDSM4(A3l, sb + a3b + 6400u + aoff);
                    mma_pair(acc3[j][0], acc3[j][1], A3h, B3h[j]);
                    mma_pair(acc3[j ^ 1][0], acc3[j ^ 1][1], A3h, B3l[j]);
                    mma_pair(acc3[j][0], acc3[j][1], A3l, B3h[j]);
                }
            }
            if (g < 6) {
#pragma unroll
                for (int n = 0; n < 2; n++) {
                    int col = np3 * 16 + n * 8 + 2 * tg;
                    int pos0 = (2 * tnum) * 6 + g;
                    int pos1 = (2 * tnum + 1) * 6 + g;
                    C3[pos0 * 33 + col] = acc3[0][n][0] + acc3[1][n][0];
                    C3[pos0 * 33 + col + 1] = acc3[0][n][1] + acc3[1][n][1];
                    C3[pos1 * 33 + col] = acc3[0][n][2] + acc3[1][n][2];
                    C3[pos1 * 33 + col + 1] = acc3[0][n][3] + acc3[1][n][3];
                }
            }
        }
        CP_WAIT0;
        TEAM_SYNC(team);
        if (active) {
            float* go = g_out3 + img * 288;
            {
                int oc = myoc, pos = ttid - oc * 9;
                int pr = pos / 3, pc = pos - pr * 3;
                const float* c0 = C3 + ((2 * pr) * 6 + 2 * pc) * 33 + oc;
                float v = fmaxf(fmaxf(c0[0], c0[33]), fmaxf(c0[6 * 33], c0[7 * 33]));
                v = fmaxf(v + __ldg(&cb3[oc]), 0.f);
                go[ttid] = v; lsum += v; lsq += v * v;
            }
            if (ttid < 32) {
                int idx = ttid + 256;
                int oc = myoc2, pos = idx - oc * 9;
                int pr = pos / 3, pc = pos - pr * 3;
                const float* c0 = C3 + ((2 * pr) * 6 + 2 * pc) * 33 + oc;
                float v = fmaxf(fmaxf(c0[0], c0[33]), fmaxf(c0[6 * 33], c0[7 * 33]));
                v = fmaxf(v + __ldg(&cb3[oc]), 0.f);
                go[idx] = v; lsum2 += v; lsq2 += v * v;
            }
        }
        {
            int imgN = img + 296;
            if (it < 13 && imgN < B)
                conv1_compute(smem, XBT(team, (it + 1) & 1), a2b, ttid);
            int imgP = img + 592;
            if (it < 12 && imgP < B)
                prefetch_x(sb, XBT(team, it & 1), x, imgP, ttid);
        }
        CP_COMMIT;
        TEAM_SYNC(team);
    }
    atomicAdd(&ssum[myoc], lsum); atomicAdd(&ssq[myoc], lsq);
    if (ttid < 32) { atomicAdd(&ssum[myoc2], lsum2); atomicAdd(&ssq[myoc2], lsq2); }
    __syncthreads();
    if (tid < 32) {
        atomicAdd(&g_stats[tid], ssum[tid]);
        atomicAdd(&g_stats[32 + tid], ssq[tid]);
    }
}

// ---------------- compose expert chain: 24 blocks (3 actions x 8 slices) --------
__global__ void __launch_bounds__(128) compose_kernel(
    const float* __restrict__ ew1, const float* __restrict__ eb1,
    const float* __restrict__ ew2, const float* __restrict__ eb2,
    const float* __restrict__ ew3, const float* __restrict__ eb3) {
    __shared__ float E3s[1280];
    __shared__ float C1s[1280];
    int tid = threadIdx.x;
    int a = blockIdx.x >> 3, s = blockIdx.x & 7;
    if (blockIdx.x == 0 && tid < 64) g_stats[tid] = 0.f;
    for (int i = tid; i < 1280; i += 128) E3s[i] = ew3[a * 1280 + i];
    __syncthreads();
    {
        float sc[10];
#pragma unroll
        for (int o = 0; o < 10; o++) sc[o] = 0.f;
        const float* e2r = ew2 + a * 16384 + tid * 128;
#pragma unroll 4
        for (int j = 0; j < 128; j++) {
            float e = e2r[j];
#pragma unroll
            for (int o = 0; o < 10; o++) sc[o] += e * E3s[j * 10 + o];
        }
#pragma unroll
        for (int o = 0; o < 10; o++) C1s[tid * 10 + o] = sc[o];
    }
    __syncthreads();
    if (s == 0 && tid < 10) {
        float bb = eb3[a * 10 + tid];
        for (int i = 0; i < 128; i++) {
            bb += eb2[a * 128 + i] * E3s[i * 10 + tid];
            bb += eb1[a * 128 + i] * C1s[i * 10 + tid];
        }
        g_bc[a * 10 + tid] = bb;
    }
    if (tid < 36) {
        int k = s * 36 + tid;
        float sc[10];
#pragma unroll
        for (int o = 0; o < 10; o++) sc[o] = 0.f;
        const float* e1r = ew1 + a * 36864 + k * 128;
#pragma unroll 4
        for (int i = 0; i < 128; i++) {
            float e = e1r[i];
#pragma unroll
            for (int o = 0; o < 10; o++) sc[o] += e * C1s[i * 10 + o];
        }
#pragma unroll
        for (int o = 0; o < 10; o++) g_Wc[(a * 288 + k) * 10 + o] = sc[o];
    }
}

// ---------------- MLP: smem-staged weights, double-buffered cp.async ------------
#define MS_SCALE 0
#define MS_YS    256
#define MS_HA    18688
#define MS_HB    26880
#define MS_WBUF  35072
#define MLP_SMEM 67840

__device__ __forceinline__ void mlp_prefetch(uint32_t sb, int ti,
                                             const float* __restrict__ pw1,
                                             const float* __restrict__ pw2, int tid) {
    const char* src = (const char*)((ti < 9) ? (pw1 + ti * 4096) : (pw2 + (ti - 9) * 4096));
    uint32_t dst = sb + MS_WBUF + (uint32_t)(ti & 1) * 16384u;
#pragma unroll
    for (int c = 0; c < 4; c++) {
        int i = tid + c * 256;
        asm volatile("cp.async.ca.shared.global [%0], [%1], 16;"
                     :: "r"(dst + (uint32_t)i * 16u), "l"(src + i * 16) : "memory");
    }
}

__global__ void __launch_bounds__(256) mlp_kernel(
    const float* __restrict__ pw1, const float* __restrict__ pb1,
    const float* __restrict__ pw2, const float* __restrict__ pb2,
    const float* __restrict__ pw3, const float* __restrict__ pb3,
    const float* __restrict__ bn_g, const float* __restrict__ bn_b,
    float* __restrict__ out, int write_actions) {
    extern __shared__ char ms[];
    uint32_t sb = smem_u32(ms);
    float* s_scale = (float*)(ms + MS_SCALE);
    float* s_shift = s_scale + 32;
    float* ys = (float*)(ms + MS_YS);
    float* ha = (float*)(ms + MS_HA);
    float* hb = (float*)(ms + MS_HB);
    int tid = threadIdx.x;
    int w = tid >> 5, lane = tid & 31;
    int e0 = blockIdx.x * 16;

    mlp_prefetch(sb, 0, pw1, pw2, tid); CP_COMMIT;
    mlp_prefetch(sb, 1, pw1, pw2, tid); CP_COMMIT;

    if (tid < 32) {
        const float inv_n = 1.0f / (float)(B * 9);
        float m = g_stats[tid] * inv_n;
        float var = g_stats[32 + tid] * inv_n - m * m;
        float sc = bn_g[tid] * rsqrtf(var + 1e-5f);
        s_scale[tid] = sc;
        s_shift[tid] = bn_b[tid] - m * sc;
    }
    __syncthreads();
    for (int idx = tid; idx < 4608; idx += 256) {
        int e = idx / 288, k = idx - e * 288, c = k / 9;
        ys[idx] = g_out3[(e0 + e) * 288 + k] * s_scale[c] + s_shift[c];
    }

    const float* y0p = ys + (2 * w) * 288;
    const float* y1p = ys + (2 * w + 1) * 288;
    float acc1[2][4], acc2[2][4];
    {
        float4 bv = *(const float4*)(pb1 + lane * 4);
        acc1[0][0] = bv.x; acc1[0][1] = bv.y; acc1[0][2] = bv.z; acc1[0][3] = bv.w;
        acc1[1][0] = bv.x; acc1[1][1] = bv.y; acc1[1][2] = bv.z; acc1[1][3] = bv.w;
        float4 bv2 = *(const float4*)(pb2 + lane * 4);
        acc2[0][0] = bv2.x; acc2[0][1] = bv2.y; acc2[0][2] = bv2.z; acc2[0][3] = bv2.w;
        acc2[1][0] = bv2.x; acc2[1][1] = bv2.y; acc2[1][2] = bv2.z; acc2[1][3] = bv2.w;
    }

    for (int ti = 0; ti < 13; ti++) {
        if (ti < 12) { CP_WAIT1; } else { CP_WAIT0; }
        __syncthreads();
        const float4* wt = (const float4*)(ms + MS_WBUF + (uint32_t)(ti & 1) * 16384u);
        if (ti < 9) {
            int kb = ti * 32;
#pragma unroll 8
            for (int kl = 0; kl < 32; kl++) {
                float4 w4 = wt[kl * 32 + lane];
                float y0 = y0p[kb + kl], y1 = y1p[kb + kl];
                acc1[0][0] += y0 * w4.x; acc1[0][1] += y0 * w4.y;
                acc1[0][2] += y0 * w4.z; acc1[0][3] += y0 * w4.w;
                acc1[1][0] += y1 * w4.x; acc1[1][1] += y1 * w4.y;
                acc1[1][2] += y1 * w4.z; acc1[1][3] += y1 * w4.w;
            }
            if (ti == 8) {
#pragma unroll
                for (int e = 0; e < 2; e++)
                    *(float4*)(ha + (2 * w + e) * 128 + lane * 4) =
                        make_float4(fmaxf(acc1[e][0], 0.f), fmaxf(acc1[e][1], 0.f),
                                    fmaxf(acc1[e][2], 0.f), fmaxf(acc1[e][3], 0.f));
            }
        } else {
            int kb = (ti - 9) * 32;
            const float* h0 = ha + (2 * w) * 128;
            const float* h1 = ha + (2 * w + 1) * 128;
#pragma unroll 8
            for (int kl = 0; kl < 32; kl++) {
                float4 w4 = wt[kl * 32 + lane];
                float y0 = h0[kb + kl], y1 = h1[kb + kl];
                acc2[0][0] += y0 * w4.x; acc2[0][1] += y0 * w4.y;
                acc2[0][2] += y0 * w4.z; acc2[0][3] += y0 * w4.w;
                acc2[1][0] += y1 * w4.x; acc2[1][1] += y1 * w4.y;
                acc2[1][2] += y1 * w4.z; acc2[1][3] += y1 * w4.w;
            }
        }
        __syncthreads();
        if (ti + 2 < 13) { mlp_prefetch(sb, ti + 2, pw1, pw2, tid); CP_COMMIT; }
    }
#pragma unroll
    for (int e = 0; e < 2; e++)
        *(float4*)(hb + (2 * w + e) * 128 + lane * 4) =
            make_float4(fmaxf(acc2[e][0], 0.f), fmaxf(acc2[e][1], 0.f),
                        fmaxf(acc2[e][2], 0.f), fmaxf(acc2[e][3], 0.f));
    __syncwarp();

    for (int e = 0; e < 2; e++) {
        int le = 2 * w + e;
        float p0 = 0.f, p1 = 0.f, p2 = 0.f;
#pragma unroll
        for (int kk = 0; kk < 4; kk++) {
            int k = lane + 32 * kk;
            float hv = hb[le * 128 + k];
            const float* wr = pw3 + k * 3;
            p0 += hv * wr[0]; p1 += hv * wr[1]; p2 += hv * wr[2];
        }
#pragma unroll
        for (int off = 16; off > 0; off >>= 1) {
            p0 += __shfl_down_sync(0xffffffffu, p0, off);
            p1 += __shfl_down_sync(0xffffffffu, p1, off);
            p2 += __shfl_down_sync(0xffffffffu, p2, off);
        }
        int a = 0;
        if (lane == 0) {
            p0 += __ldg(&pb3[0]); p1 += __ldg(&pb3[1]); p2 += __ldg(&pb3[2]);
            float best = p0;
            if (p1 > best) { best = p1; a = 1; }
            if (p2 > best) { a = 2; }
        }
        a = __shfl_sync(0xffffffffu, a, 0);
        float po[10];
#pragma unroll
        for (int o = 0; o < 10; o++) po[o] = 0.f;
        const float* Wb = g_Wc + a * 2880;
        const float* ye = ys + le * 288;
#pragma unroll
        for (int kk = 0; kk < 9; kk++) {
            int k = lane + 32 * kk;
            float yv = ye[k];
            const float* wr = Wb + k * 10;
#pragma unroll
            for (int o = 0; o < 10; o++) po[o] += yv * wr[o];
        }
#pragma unroll
        for (int off = 16; off > 0; off >>= 1) {
#pragma unroll
            for (int o = 0; o < 10; o++) po[o] += __shfl_down_sync(0xffffffffu, po[o], off);
        }
        if (lane == 0) {
            int gg = e0 + le;
#pragma unroll
            for (int o = 0; o < 10; o++) out[gg * 10 + o] = po[o] + g_bc[a * 10 + o];
            if (write_actions) out[B * 10 + gg] = (float)a;
        }
    }
}

// ---------------- launch --------------------------------------------------------
extern "C" void kernel_launch(void* const* d_in, const int* in_sizes, int n_in,
                              void* d_out, int out_size) {
    const float* x    = (const float*)d_in[0];
    const float* cw1  = (const float*)d_in[1];
    const float* cb1  = (const float*)d_in[2];
    const float* cw2  = (const float*)d_in[3];
    const float* cb2  = (const float*)d_in[4];
    const float* cw3  = (const float*)d_in[5];
    const float* cb3  = (const float*)d_in[6];
    const float* bn_g = (const float*)d_in[7];
    const float* bn_b = (const float*)d_in[8];
    const float* pw1  = (const float*)d_in[9];
    const float* pb1  = (const float*)d_in[10];
    const float* pw2  = (const float*)d_in[11];
    const float* pb2  = (const float*)d_in[12];
    const float* pw3  = (const float*)d_in[13];
    const float* pb3  = (const float*)d_in[14];
    const float* ew1  = (const float*)d_in[15];
    const float* eb1  = (const float*)d_in[16];
    const float* ew2  = (const float*)d_in[17];
    const float* eb2  = (const float*)d_in[18];
    const float* ew3  = (const float*)d_in[19];
    const float* eb3  = (const float*)d_in[20];
    float* out = (float*)d_out;
    int write_actions = (out_size >= B * 10 + B) ? 1 : 0;

    cudaFuncSetAttribute(conv123_kernel, cudaFuncAttributeMaxDynamicSharedMemorySize, SM_TOTAL);
    cudaFuncSetAttribute(mlp_kernel, cudaFuncAttributeMaxDynamicSharedMemorySize, MLP_SMEM);

    compose_kernel<<<24, 128>>>(ew1, eb1, ew2, eb2, ew3, eb3);                // 1 (also zeroes g_stats)
    conv123_kernel<<<148, 512, SM_TOTAL>>>(x, cw1, cb1, cw2, cb2, cw3, cb3);  // 2
    mlp_kernel<<<B / 16, 256, MLP_SMEM>>>(pw1, pb1, pw2, pb2, pw3, pb3,
                                          bn_g, bn_b, out, write_actions);    // 3
}

// round 16
// speedup vs baseline: 1.0715x; 1.0566x over previous
#include <cuda_runtime.h>
#include <cuda_bf16.h>
#include <cuda_fp16.h>
#include <cstdint>

#define B 4096

__device__ float g_out3[B * 288];    // conv3 out (pre-BN), [b][oc*9+pos]
__device__ float g_stats[64];
__device__ float g_Wc[3 * 288 * 10];
__device__ float g_bc[30];

// ---------------- portable tensor-core helpers (sm_80+ PTX only) ---------------
__device__ __forceinline__ uint32_t smem_u32(const void* p) {
    uint32_t a;
    asm("{ .reg .u64 t; cvta.to.shared.u64 t, %1; cvt.u32.u64 %0, t; }" : "=r"(a) : "l"(p));
    return a;
}
#define LDSM4(r, addr) \
    asm volatile("ldmatrix.sync.aligned.m8n8.x4.shared.b16 {%0,%1,%2,%3}, [%4];" \
                 : "=r"((r)[0]), "=r"((r)[1]), "=r"((r)[2]), "=r"((r)[3]) : "r"(addr))
__device__ __forceinline__ void mma16816(float* c, const uint32_t a[4], uint32_t b0, uint32_t b1) {
    asm volatile("mma.sync.aligned.m16n8k16.row.col.f32.f16.f16.f32 "
                 "{%0,%1,%2,%3}, {%4,%5,%6,%7}, {%8,%9}, {%0,%1,%2,%3};"
                 : "+f"(c[0]), "+f"(c[1]), "+f"(c[2]), "+f"(c[3])
                 : "r"(a[0]), "r"(a[1]), "r"(a[2]), "r"(a[3]), "r"(b0), "r"(b1));
}
__device__ __forceinline__ void mma_pair(float* c0, float* c1, const uint32_t a[4], const uint32_t b[4]) {
    mma16816(c0, a, b[0], b[1]);
    mma16816(c1, a, b[2], b[3]);
}
__device__ __forceinline__ void split_store(char* smem, uint32_t oh, uint32_t ol, float v) {
    __half h = __float2half_rn(v);
    __half l = __float2half_rn(v - __half2float(h));
    *(__half*)(smem + oh) = h;
    *(__half*)(smem + ol) = l;
}
#define CP_COMMIT asm volatile("cp.async.commit_group;")
#define CP_WAIT0  asm volatile("cp.async.wait_group 0;" ::: "memory")
#define CP_WAIT1  asm volatile("cp.async.wait_group 1;" ::: "memory")
#define TEAM_SYNC(team) asm volatile("bar.sync %0, 256;" :: "r"((team) + 1) : "memory")

// ---------------- fully fused conv1+conv2+conv3 (R13 known-good) ----------------
#define SAS 40
#define SM_B   1024
#define SB_MAT 2560
#define A2T(team) (93184u + (uint32_t)(team) * 40960u)
#define A3T(team) (175104u + (uint32_t)(team) * 12800u)
#define C3T(team) (200704u + (uint32_t)(team) * 4752u)
#define XBT(team, buf) (210240u + (uint32_t)(team) * 6272u + (uint32_t)(buf) * 3136u)
#define SM_W1S 222784u
#define SM_B1S 223936u
#define SM_TOTAL 224064

__device__ __forceinline__ void prefetch_x(uint32_t sb, uint32_t xoff,
                                           const float* __restrict__ x, int img, int ttid) {
    if (ttid < 196) {
        uint32_t dst = sb + xoff + (uint32_t)ttid * 16u;
        const char* src = (const char*)(x + (size_t)img * 784) + ttid * 16;
        asm volatile("cp.async.ca.shared.global [%0], [%1], 16;" :: "r"(dst), "l"(src));
    }
}

__device__ __forceinline__ void zero_pads(char* smem, uint32_t bufbase, int ttid) {
    for (int z = ttid; z < 600; z += 256) {
        int si = z / 300, r = z - si * 300;
        int ri = r / 5, q = r - ri * 5;
        int row;
        if (ri < 17) row = ri;
        else if (ri < 43) { int k = ri - 17; row = (k >> 1) * 16 + 31 + (k & 1); }
        else row = 239 + (ri - 43);
        *(float4*)(smem + bufbase + si * 20480 + row * 80 + q * 16) =
            make_float4(0.f, 0.f, 0.f, 0.f);
    }
}

__device__ void conv1_compute(char* smem, uint32_t xoff, uint32_t a2b, int ttid) {
    const float* xs = (const float*)(smem + xoff);
    const float* w1s = (const float*)(smem + SM_W1S);
    const float* b1s = (const float*)(smem + SM_B1S);
    for (int u = ttid; u < 784; u += 256) {
        int pos = u >> 2, ocg = u & 3;
        int ph = pos / 14, pw = pos - ph * 14;
        float p[4][4];
#pragma unroll
        for (int r = 0; r < 4; r++) {
            int ir = 2 * ph - 1 + r;
#pragma unroll
            for (int c = 0; c < 4; c++) {
                int icx = 2 * pw - 1 + c;
                p[r][c] = (ir >= 0 && ir < 28 && icx >= 0 && icx < 28) ? xs[ir * 28 + icx] : 0.f;
            }
        }
        uint32_t rowoff = (uint32_t)((((ph + 1) * 16) + pw + 1) * SAS) * 2;
#pragma unroll 2
        for (int o8 = 0; o8 < 8; o8++) {
            int oc = ocg * 8 + o8;
            const float* w = w1s + oc * 9;
            float a0 = 0.f, a1 = 0.f, a2 = 0.f, a3 = 0.f;
#pragma unroll
            for (int kh = 0; kh < 3; kh++)
#pragma unroll
                for (int kw = 0; kw < 3; kw++) {
                    float wv = w[kh * 3 + kw];
                    a0 += p[kh][kw] * wv;     a1 += p[kh][kw + 1] * wv;
                    a2 += p[kh + 1][kw] * wv; a3 += p[kh + 1][kw + 1] * wv;
                }
            float v = fmaxf(fmaxf(fmaxf(a0, a1), fmaxf(a2, a3)) + b1s[oc], 0.f);
            uint32_t off = rowoff + (uint32_t)oc * 2u;
            split_store(smem, a2b + off, a2b + 20480u + off, v);
        }
    }
}

__global__ void __launch_bounds__(512, 1) conv123_kernel(
    const float* __restrict__ x,
    const float* __restrict__ cw1, const float* __restrict__ cb1,
    const float* __restrict__ cw2, const float* __restrict__ cb2,
    const float* __restrict__ cw3, const float* __restrict__ cb3) {
    extern __shared__ char smem[];
    uint32_t sb = smem_u32(smem);
    int tid = threadIdx.x;
    int team = tid >> 8, ttid = tid & 255;
    int wid = ttid >> 5, lane = tid & 31;
    float* ssum = (float*)(smem + 64);
    float* ssq  = (float*)(smem + 192);
    uint32_t a2b = A2T(team), a3b = A3T(team), c3b = C3T(team);
    float* C3 = (float*)(smem + c3b);
    int first_img = blockIdx.x + 148 * team;

    if (tid < 32) { ssum[tid] = 0.f; ssq[tid] = 0.f; }
    for (int i = tid; i < 1600; i += 512)
        ((float4*)(smem + A3T(0)))[i] = make_float4(0.f, 0.f, 0.f, 0.f);
    for (int idx = tid; idx < 18432; idx += 512) {
        int conv = idx / 9216, r = idx % 9216;
        int tap = r / 1024, r2 = r % 1024;
        int oc = r2 >> 5, ic = r2 & 31;
        int kh = tap / 3, kw = tap % 3;
        float w = __ldg(&(conv ? cw3 : cw2)[oc * 288 + ic * 9 + kh * 3 + kw]);
        uint32_t bh = SM_B + (uint32_t)((conv * 9 + tap) * 2) * SB_MAT + (oc * SAS + ic) * 2;
        split_store(smem, bh, bh + SB_MAT, w);
    }
    for (int i = tid; i < 288; i += 512) ((float*)(smem + SM_W1S))[i] = cw1[i];
    if (tid < 32) ((float*)(smem + SM_B1S))[tid] = cb1[tid];
    zero_pads(smem, a2b, ttid);
    prefetch_x(sb, XBT(team, 0), x, first_img, ttid);
    CP_COMMIT;
    CP_WAIT0;
    __syncthreads();
    conv1_compute(smem, XBT(team, 0), a2b, ttid);
    if (first_img + 296 < B) prefetch_x(sb, XBT(team, 1), x, first_img + 296, ttid);
    CP_COMMIT;
    TEAM_SYNC(team);

    int g = lane >> 2, tg = lane & 3;
    uint32_t a_r = (uint32_t)(lane & 15), a_c = (uint32_t)((lane >> 4) * 8);
    uint32_t b_row = (uint32_t)(((lane >> 4) << 3) + (lane & 7));
    uint32_t b_c = (uint32_t)((lane & 8) ? 8 : 0);
    float lsum = 0.f, lsq = 0.f, lsum2 = 0.f, lsq2 = 0.f;
    int myoc = ttid / 9, myoc2 = (ttid + 256) / 9;
    int mt[2] = { 2 * wid + 1, 2 * wid + 2 };
    int cv2 = wid < 7;
    int tnum = wid >> 1, np3 = wid & 1;
    float bias0[4], bias1[4];
#pragma unroll
    for (int n = 0; n < 4; n++) {
        bias0[n] = __ldg(&cb2[n * 8 + 2 * tg]);
        bias1[n] = __ldg(&cb2[n * 8 + 2 * tg + 1]);
    }

    for (int it = 0; it < 14; it++) {
        int img = first_img + 296 * it;
        int active = img < B;
        if (cv2) {
            float acc[2][4][4];
#pragma unroll
            for (int t = 0; t < 2; t++)
#pragma unroll
                for (int n = 0; n < 4; n++)
#pragma unroll
                    for (int i = 0; i < 4; i++) acc[t][n][i] = 0.f;
#pragma unroll
            for (int tap = 0; tap < 9; tap++) {
                uint32_t bmat = sb + SM_B + (uint32_t)(tap * 2) * SB_MAT;
                uint32_t Bh[2][2][4], Bl[2][2][4];
#pragma unroll
                for (int np = 0; np < 2; np++)
#pragma unroll
                    for (int j = 0; j < 2; j++) {
                        uint32_t boff = (((uint32_t)np * 16 + b_row) * SAS + (uint32_t)j * 16 + b_c) * 2;
                        LDSM4(Bh[np][j], bmat + boff);
                        LDSM4(Bl[np][j], bmat + SB_MAT + boff);
                    }
                int dr = (tap / 3 - 1) * 16 + (tap % 3 - 1) + 1;
#pragma unroll
                for (int j = 0; j < 2; j++) {
                    uint32_t Ah[2][4], Al[2][4];
#pragma unroll
                    for (int t = 0; t < 2; t++) {
                        uint32_t aoff = (uint32_t)((mt[t] * 16 + dr + (int)a_r) * SAS) * 2
                                        + ((uint32_t)j * 16 + a_c) * 2;
                        LDSM4(Ah[t], sb + a2b + aoff);
                        LDSM4(Al[t], sb + a2b + 20480u + aoff);
                    }
#pragma unroll
                    for (int t = 0; t < 2; t++) {
                        mma_pair(acc[t][0], acc[t][1], Ah[t], Bh[0][j]);
                        mma_pair(acc[t][2], acc[t][3], Ah[t], Bh[1][j]);
                    }
#pragma unroll
                    for (int t = 0; t < 2; t++) {
                        mma_pair(acc[t][0], acc[t][1], Ah[t], Bl[0][j]);
                        mma_pair(acc[t][2], acc[t][3], Ah[t], Bl[1][j]);
                    }
#pragma unroll
                    for (int t = 0; t < 2; t++) {
                        mma_pair(acc[t][0], acc[t][1], Al[t], Bh[0][j]);
                        mma_pair(acc[t][2], acc[t][3], Al[t], Bh[1][j]);
                    }
                }
            }
#pragma unroll
            for (int n = 0; n < 4; n++) {
                float vA0 = fmaxf(acc[0][n][0], acc[1][n][0]);
                float vA1 = fmaxf(acc[0][n][1], acc[1][n][1]);
                float vB0 = fmaxf(acc[0][n][2], acc[1][n][2]);
                float vB1 = fmaxf(acc[0][n][3], acc[1][n][3]);
                float qA0 = fmaxf(vA0, __shfl_xor_sync(0xffffffffu, vA0, 4));
                float qA1 = fmaxf(vA1, __shfl_xor_sync(0xffffffffu, vA1, 4));
                float qB0 = fmaxf(vB0, __shfl_xor_sync(0xffffffffu, vB0, 4));
                float qB1 = fmaxf(vB1, __shfl_xor_sync(0xffffffffu, vB1, 4));
                if ((g & 1) == 0) {
                    int oc0 = n * 8 + 2 * tg;
                    int pcA = g >> 1;
                    uint32_t rowA = (uint32_t)((wid + 2) * 8 + pcA);
                    uint32_t offA = (rowA * SAS + (uint32_t)oc0) * 2;
                    split_store(smem, a3b + offA, a3b + 6400u + offA,
                                fmaxf(qA0 + bias0[n], 0.f));
                    split_store(smem, a3b + offA + 2, a3b + 6400u + offA + 2,
                                fmaxf(qA1 + bias1[n], 0.f));
                    int pcB = (g >> 1) + 4;
                    if (pcB < 7) {
                        uint32_t rowB = (uint32_t)((wid + 2) * 8 + pcB);
                        uint32_t offB = (rowB * SAS + (uint32_t)oc0) * 2;
                        split_store(smem, a3b + offB, a3b + 6400u + offB,
                                    fmaxf(qB0 + bias0[n], 0.f));
                        split_store(smem, a3b + offB + 2, a3b + 6400u + offB + 2,
                                    fmaxf(qB1 + bias1[n], 0.f));
                    }
                }
            }
        }
        TEAM_SYNC(team);
        if (wid < 6) {
            float acc3[2][2][4];
#pragma unroll
            for (int bk = 0; bk < 2; bk++)
#pragma unroll
                for (int n = 0; n < 2; n++)
#pragma unroll
                    for (int i = 0; i < 4; i++) acc3[bk][n][i] = 0.f;
            int base = 16 + tnum * 16;
#pragma unroll
            for (int tap = 0; tap < 9; tap++) {
                uint32_t bmat = sb + SM_B + (uint32_t)(18 + tap * 2) * SB_MAT;
                uint32_t B3h[2][4], B3l[2][4];
#pragma unroll
                for (int j = 0; j < 2; j++) {
                    uint32_t boff = (((uint32_t)np3 * 16 + b_row) * SAS + (uint32_t)j * 16 + b_c) * 2;
                    LDSM4(B3h[j], bmat + boff);
                    LDSM4(B3l[j], bmat + SB_MAT + boff);
                }
                int dr3 = (tap / 3 - 1) * 8 + (tap % 3 - 1);
#pragma unroll
                for (int j = 0; j < 2; j++) {
                    uint32_t aoff = (uint32_t)((base + dr3 + (int)a_r) * SAS) * 2
                                    + ((uint32_t)j * 16 + a_c) * 2;
                    uint32_t A3h[4], A3l[4];
                    LDSM4(A3h, sb + a3b + aoff);
                    LDSM4(A3l, sb + a3b + 6400u + aoff);
                    mma_pair(acc3[j][0], acc3[j][1], A3h, B3h[j]);
                    mma_pair(acc3[j ^ 1][0], acc3[j ^ 1][1], A3h, B3l[j]);
                    mma_pair(acc3[j][0], acc3[j][1], A3l, B3h[j]);
                }
            }
            if (g < 6) {
#pragma unroll
                for (int n = 0; n < 2; n++) {
                    int col = np3 * 16 + n * 8 + 2 * tg;
                    int pos0 = (2 * tnum) * 6 + g;
                    int pos1 = (2 * tnum + 1) * 6 + g;
                    C3[pos0 * 33 + col] = acc3[0][n][0] + acc3[1][n][0];
                    C3[pos0 * 33 + col + 1] = acc3[0][n][1] + acc3[1][n][1];
                    C3[pos1 * 33 + col] = acc3[0][n][2] + acc3[1][n][2];
                    C3[pos1 * 33 + col + 1] = acc3[0][n][3] + acc3[1][n][3];
                }
            }
        }
        CP_WAIT0;
        TEAM_SYNC(team);
        if (active) {
            float* go = g_out3 + img * 288;
            {
                int oc = myoc, pos = ttid - oc * 9;
                int pr = pos / 3, pc = pos - pr * 3;
                const float* c0 = C3 + ((2 * pr) * 6 + 2 * pc) * 33 + oc;
                float v = fmaxf(fmaxf(c0[0], c0[33]), fmaxf(c0[6 * 33], c0[7 * 33]));
                v = fmaxf(v + __ldg(&cb3[oc]), 0.f);
                go[ttid] = v; lsum += v; lsq += v * v;
            }
            if (ttid < 32) {
                int idx = ttid + 256;
                int oc = myoc2, pos = idx - oc * 9;
                int pr = pos / 3, pc = pos - pr * 3;
                const float* c0 = C3 + ((2 * pr) * 6 + 2 * pc) * 33 + oc;
                float v = fmaxf(fmaxf(c0[0], c0[33]), fmaxf(c0[6 * 33], c0[7 * 33]));
                v = fmaxf(v + __ldg(&cb3[oc]), 0.f);
                go[idx] = v; lsum2 += v; lsq2 += v * v;
            }
        }
        {
            int imgN = img + 296;
            if (it < 13 && imgN < B)
                conv1_compute(smem, XBT(team, (it + 1) & 1), a2b, ttid);
            int imgP = img + 592;
            if (it < 12 && imgP < B)
                prefetch_x(sb, XBT(team, it & 1), x, imgP, ttid);
        }
        CP_COMMIT;
        TEAM_SYNC(team);
    }
    atomicAdd(&ssum[myoc], lsum); atomicAdd(&ssq[myoc], lsq);
    if (ttid < 32) { atomicAdd(&ssum[myoc2], lsum2); atomicAdd(&ssq[myoc2], lsq2); }
    __syncthreads();
    if (tid < 32) {
        atomicAdd(&g_stats[tid], ssum[tid]);
        atomicAdd(&g_stats[32 + tid], ssq[tid]);
    }
}

// ---------------- compose: smem-staged (cp.async), 24 blocks --------------------
#define CM_E3 0
#define CM_C1 5120
#define CM_E2 10240
#define CM_W1 75776
#define CM_TOTAL 94208

__global__ void __launch_bounds__(128) compose_kernel(
    const float* __restrict__ ew1, const float* __restrict__ eb1,
    const float* __restrict__ ew2, const float* __restrict__ eb2,
    const float* __restrict__ ew3, const float* __restrict__ eb3) {
    extern __shared__ char cs[];
    uint32_t sb = smem_u32(cs);
    float* E3s = (float*)(cs + CM_E3);
    float* C1s = (float*)(cs + CM_C1);
    float* E2s = (float*)(cs + CM_E2);
    float* W1s = (float*)(cs + CM_W1);
    int tid = threadIdx.x;
    int a = blockIdx.x >> 3, s = blockIdx.x & 7;
    if (blockIdx.x == 0 && tid < 64) g_stats[tid] = 0.f;

    // group 1: E2 (64 KB)
    {
        const char* src = (const char*)(ew2 + a * 16384);
#pragma unroll
        for (int c = 0; c < 32; c++) {
            int i = tid + c * 128;
            asm volatile("cp.async.ca.shared.global [%0], [%1], 16;"
                         :: "r"(sb + CM_E2 + (uint32_t)i * 16u), "l"(src + i * 16));
        }
    }
    CP_COMMIT;
    // group 2: ew1 slice (18 KB)
    {
        const char* src = (const char*)(ew1 + a * 36864 + s * 4608);
#pragma unroll
        for (int c = 0; c < 9; c++) {
            int i = tid + c * 128;
            asm volatile("cp.async.ca.shared.global [%0], [%1], 16;"
                         :: "r"(sb + CM_W1 + (uint32_t)i * 16u), "l"(src + i * 16));
        }
    }
    CP_COMMIT;
    for (int i = tid; i < 1280; i += 128) E3s[i] = ew3[a * 1280 + i];
    CP_WAIT1;          // E2 landed
    __syncthreads();
    // C1s = E2 @ E3 (from smem)
    {
        float sc[10];
#pragma unroll
        for (int o = 0; o < 10; o++) sc[o] = 0.f;
        const float* e2r = E2s + tid * 128;
#pragma unroll 4
        for (int j = 0; j < 128; j++) {
            float e = e2r[j];
#pragma unroll
            for (int o = 0; o < 10; o++) sc[o] += e * E3s[j * 10 + o];
        }
#pragma unroll
        for (int o = 0; o < 10; o++) C1s[tid * 10 + o] = sc[o];
    }
    __syncthreads();
    if (s == 0) {
        // stage eb1/eb2 into (now free) E2s, then combine
        E2s[tid] = eb1[a * 128 + tid];
        E2s[128 + tid] = eb2[a * 128 + tid];
        __syncthreads();
        if (tid < 10) {
            float bb = eb3[a * 10 + tid];
#pragma unroll 4
            for (int i = 0; i < 128; i++) {
                bb += E2s[128 + i] * E3s[i * 10 + tid];
                bb += E2s[i] * C1s[i * 10 + tid];
            }
            g_bc[a * 10 + tid] = bb;
        }
    }
    CP_WAIT0;          // ew1 slice landed
    __syncthreads();
    if (tid < 36) {
        int k = s * 36 + tid;
        float sc[10];
#pragma unroll
        for (int o = 0; o < 10; o++) sc[o] = 0.f;
        const float* e1r = W1s + tid * 128;
#pragma unroll 4
        for (int i = 0; i < 128; i++) {
            float e = e1r[i];
#pragma unroll
            for (int o = 0; o < 10; o++) sc[o] += e * C1s[i * 10 + o];
        }
#pragma unroll
        for (int o = 0; o < 10; o++) g_Wc[(a * 288 + k) * 10 + o] = sc[o];
    }
}

// ---------------- MLP: smem-staged weights, double-buffered cp.async ------------
#define MS_SCALE 0
#define MS_YS    256
#define MS_HA    18688
#define MS_HB    26880
#define MS_WBUF  35072
#define MLP_SMEM 67840

__device__ __forceinline__ void mlp_prefetch(uint32_t sb, int ti,
                                             const float* __restrict__ pw1,
                                             const float* __restrict__ pw2, int tid) {
    const char* src = (const char*)((ti < 9) ? (pw1 + ti * 4096) : (pw2 + (ti - 9) * 4096));
    uint32_t dst = sb + MS_WBUF + (uint32_t)(ti & 1) * 16384u;
#pragma unroll
    for (int c = 0; c < 4; c++) {
        int i = tid + c * 256;
        asm volatile("cp.async.ca.shared.global [%0], [%1], 16;"
                     :: "r"(dst + (uint32_t)i * 16u), "l"(src + i * 16) : "memory");
    }
}

__global__ void __launch_bounds__(256) mlp_kernel(
    const float* __restrict__ pw1, const float* __restrict__ pb1,
    const float* __restrict__ pw2, const float* __restrict__ pb2,
    const float* __restrict__ pw3, const float* __restrict__ pb3,
    const float* __restrict__ bn_g, const float* __restrict__ bn_b,
    float* __restrict__ out, int write_actions) {
    extern __shared__ char ms[];
    uint32_t sb = smem_u32(ms);
    float* s_scale = (float*)(ms + MS_SCALE);
    float* s_shift = s_scale + 32;
    float* ys = (float*)(ms + MS_YS);
    float* ha = (float*)(ms + MS_HA);
    float* hb = (float*)(ms + MS_HB);
    int tid = threadIdx.x;
    int w = tid >> 5, lane = tid & 31;
    int e0 = blockIdx.x * 16;

    mlp_prefetch(sb, 0, pw1, pw2, tid); CP_COMMIT;
    mlp_prefetch(sb, 1, pw1, pw2, tid); CP_COMMIT;

    if (tid < 32) {
        const float inv_n = 1.0f / (float)(B * 9);
        float m = g_stats[tid] * inv_n;
        float var = g_stats[32 + tid] * inv_n - m * m;
        float sc = bn_g[tid] * rsqrtf(var + 1e-5f);
        s_scale[tid] = sc;
        s_shift[tid] = bn_b[tid] - m * sc;
    }
    __syncthreads();
    for (int idx = tid; idx < 4608; idx += 256) {
        int e = idx / 288, k = idx - e * 288, c = k / 9;
        ys[idx] = g_out3[(e0 + e) * 288 + k] * s_scale[c] + s_shift[c];
    }

    const float* y0p = ys + (2 * w) * 288;
    const float* y1p = ys + (2 * w + 1) * 288;
    float acc1[2][4], acc2[2][4];
    {
        float4 bv = *(const float4*)(pb1 + lane * 4);
        acc1[0][0] = bv.x; acc1[0][1] = bv.y; acc1[0][2] = bv.z; acc1[0][3] = bv.w;
        acc1[1][0] = bv.x; acc1[1][1] = bv.y; acc1[1][2] = bv.z; acc1[1][3] = bv.w;
        float4 bv2 = *(const float4*)(pb2 + lane * 4);
        acc2[0][0] = bv2.x; acc2[0][1] = bv2.y; acc2[0][2] = bv2.z; acc2[0][3] = bv2.w;
        acc2[1][0] = bv2.x; acc2[1][1] = bv2.y; acc2[1][2] = bv2.z; acc2[1][3] = bv2.w;
    }

    for (int ti = 0; ti < 13; ti++) {
        if (ti < 12) { CP_WAIT1; } else { CP_WAIT0; }
        __syncthreads();
        const float4* wt = (const float4*)(ms + MS_WBUF + (uint32_t)(ti & 1) * 16384u);
        if (ti < 9) {
            int kb = ti * 32;
#pragma unroll 8
            for (int kl = 0; kl < 32; kl++) {
                float4 w4 = wt[kl * 32 + lane];
                float y0 = y0p[kb + kl], y1 = y1p[kb + kl];
                acc1[0][0] += y0 * w4.x; acc1[0][1] += y0 * w4.y;
                acc1[0][2] += y0 * w4.z; acc1[0][3] += y0 * w4.w;
                acc1[1][0] += y1 * w4.x; acc1[1][1] += y1 * w4.y;
                acc1[1][2] += y1 * w4.z; acc1[1][3] += y1 * w4.w;
            }
            if (ti == 8) {
#pragma unroll
                for (int e = 0; e < 2; e++)
                    *(float4*)(ha + (2 * w + e) * 128 + lane * 4) =
                        make_float4(fmaxf(acc1[e][0], 0.f), fmaxf(acc1[e][1], 0.f),
                                    fmaxf(acc1[e][2], 0.f), fmaxf(acc1[e][3], 0.f));
            }
        } else {
            int kb = (ti - 9) * 32;
            const float* h0 = ha + (2 * w) * 128;
            const float* h1 = ha + (2 * w + 1) * 128;
#pragma unroll 8
            for (int kl = 0; kl < 32; kl++) {
                float4 w4 = wt[kl * 32 + lane];
                float y0 = h0[kb + kl], y1 = h1[kb + kl];
                acc2[0][0] += y0 * w4.x; acc2[0][1] += y0 * w4.y;
                acc2[0][2] += y0 * w4.z; acc2[0][3] += y0 * w4.w;
                acc2[1][0] += y1 * w4.x; acc2[1][1] += y1 * w4.y;
                acc2[1][2] += y1 * w4.z; acc2[1][3] += y1 * w4.w;
            }
        }
        __syncthreads();
        if (ti + 2 < 13) { mlp_prefetch(sb, ti + 2, pw1, pw2, tid); CP_COMMIT; }
    }
#pragma unroll
    for (int e = 0; e < 2; e++)
        *(float4*)(hb + (2 * w + e) * 128 + lane * 4) =
            make_float4(fmaxf(acc2[e][0], 0.f), fmaxf(acc2[e][1], 0.f),
                        fmaxf(acc2[e][2], 0.f), fmaxf(acc2[e][3], 0.f));
    __syncwarp();

    for (int e = 0; e < 2; e++) {
        int le = 2 * w + e;
        float p0 = 0.f, p1 = 0.f, p2 = 0.f;
#pragma unroll
        for (int kk = 0; kk < 4; kk++) {
            int k = lane + 32 * kk;
            float hv = hb[le * 128 + k];
            const float* wr = pw3 + k * 3;
            p0 += hv * wr[0]; p1 += hv * wr[1]; p2 += hv * wr[2];
        }
#pragma unroll
        for (int off = 16; off > 0; off >>= 1) {
            p0 += __shfl_down_sync(0xffffffffu, p0, off);
            p1 += __shfl_down_sync(0xffffffffu, p1, off);
            p2 += __shfl_down_sync(0xffffffffu, p2, off);
        }
        int a = 0;
        if (lane == 0) {
            p0 += __ldg(&pb3[0]); p1 += __ldg(&pb3[1]); p2 += __ldg(&pb3[2]);
            float best = p0;
            if (p1 > best) { best = p1; a = 1; }
            if (p2 > best) { a = 2; }
        }
        a = __shfl_sync(0xffffffffu, a, 0);
        float po[10];
#pragma unroll
        for (int o = 0; o < 10; o++) po[o] = 0.f;
        const float* Wb = g_Wc + a * 2880;
        const float* ye = ys + le * 288;
#pragma unroll
        for (int kk = 0; kk < 9; kk++) {
            int k = lane + 32 * kk;
            float yv = ye[k];
            const float* wr = Wb + k * 10;
#pragma unroll
            for (int o = 0; o < 10; o++) po[o] += yv * wr[o];
        }
#pragma unroll
        for (int off = 16; off > 0; off >>= 1) {
#pragma unroll
            for (int o = 0; o < 10; o++) po[o] += __shfl_down_sync(0xffffffffu, po[o], off);
        }
        if (lane == 0) {
            int gg = e0 + le;
#pragma unroll
            for (int o = 0; o < 10; o++) out[gg * 10 + o] = po[o] + g_bc[a * 10 + o];
            if (write_actions) out[B * 10 + gg] = (float)a;
        }
    }
}

// ---------------- launch --------------------------------------------------------
extern "C" void kernel_launch(void* const* d_in, const int* in_sizes, int n_in,
                              void* d_out, int out_size) {
    const float* x    = (const float*)d_in[0];
    const float* cw1  = (const float*)d_in[1];
    const float* cb1  = (const float*)d_in[2];
    const float* cw2  = (const float*)d_in[3];
    const float* cb2  = (const float*)d_in[4];
    const float* cw3  = (const float*)d_in[5];
    const float* cb3  = (const float*)d_in[6];
    const float* bn_g = (const float*)d_in[7];
    const float* bn_b = (const float*)d_in[8];
    const float* pw1  = (const float*)d_in[9];
    const float* pb1  = (const float*)d_in[10];
    const float* pw2  = (const float*)d_in[11];
    const float* pb2  = (const float*)d_in[12];
    const float* pw3  = (const float*)d_in[13];
    const float* pb3  = (const float*)d_in[14];
    const float* ew1  = (const float*)d_in[15];
    const float* eb1  = (const float*)d_in[16];
    const float* ew2  = (const float*)d_in[17];
    const float* eb2  = (const float*)d_in[18];
    const float* ew3  = (const float*)d_in[19];
    const float* eb3  = (const float*)d_in[20];
    float* out = (float*)d_out;
    int write_actions = (out_size >= B * 10 + B) ? 1 : 0;

    cudaFuncSetAttribute(conv123_kernel, cudaFuncAttributeMaxDynamicSharedMemorySize, SM_TOTAL);
    cudaFuncSetAttribute(mlp_kernel, cudaFuncAttributeMaxDynamicSharedMemorySize, MLP_SMEM);
    cudaFuncSetAttribute(compose_kernel, cudaFuncAttributeMaxDynamicSharedMemorySize, CM_TOTAL);

    compose_kernel<<<24, 128, CM_TOTAL>>>(ew1, eb1, ew2, eb2, ew3, eb3);      // 1 (also zeroes g_stats)
    conv123_kernel<<<148, 512, SM_TOTAL>>>(x, cw1, cb1, cw2, cb2, cw3, cb3);  // 2
    mlp_kernel<<<B / 16, 256, MLP_SMEM>>>(pw1, pb1, pw2, pb2, pw3, pb3,
                                          bn_g, bn_b, out, write_actions);    // 3
}

// round 17
// speedup vs baseline: 1.0856x; 1.0131x over previous
#include <cuda_runtime.h>
#include <cuda_bf16.h>
#include <cuda_fp16.h>
#include <cstdint>

#define B 4096

__device__ float g_out3[B * 288];    // conv3 out (pre-BN), [b][oc*9+pos]
__device__ float g_stats[64];
__device__ float g_Wc[3 * 288 * 10];
__device__ float g_bc[30];

// ---------------- portable tensor-core helpers (sm_80+ PTX only) ---------------
__device__ __forceinline__ uint32_t smem_u32(const void* p) {
    uint32_t a;
    asm("{ .reg .u64 t; cvta.to.shared.u64 t, %1; cvt.u32.u64 %0, t; }" : "=r"(a) : "l"(p));
    return a;
}
#define LDSM4(r, addr) \
    asm volatile("ldmatrix.sync.aligned.m8n8.x4.shared.b16 {%0,%1,%2,%3}, [%4];" \
                 : "=r"((r)[0]), "=r"((r)[1]), "=r"((r)[2]), "=r"((r)[3]) : "r"(addr))
__device__ __forceinline__ void mma16816(float* c, const uint32_t a[4], uint32_t b0, uint32_t b1) {
    asm volatile("mma.sync.aligned.m16n8k16.row.col.f32.f16.f16.f32 "
                 "{%0,%1,%2,%3}, {%4,%5,%6,%7}, {%8,%9}, {%0,%1,%2,%3};"
                 : "+f"(c[0]), "+f"(c[1]), "+f"(c[2]), "+f"(c[3])
                 : "r"(a[0]), "r"(a[1]), "r"(a[2]), "r"(a[3]), "r"(b0), "r"(b1));
}
__device__ __forceinline__ void mma_pair(float* c0, float* c1, const uint32_t a[4], const uint32_t b[4]) {
    mma16816(c0, a, b[0], b[1]);
    mma16816(c1, a, b[2], b[3]);
}
__device__ __forceinline__ void split_store(char* smem, uint32_t oh, uint32_t ol, float v) {
    __half h = __float2half_rn(v);
    __half l = __float2half_rn(v - __half2float(h));
    *(__half*)(smem + oh) = h;
    *(__half*)(smem + ol) = l;
}
#define CP_COMMIT asm volatile("cp.async.commit_group;")
#define CP_WAIT0  asm volatile("cp.async.wait_group 0;" ::: "memory")
#define CP_WAIT1  asm volatile("cp.async.wait_group 1;" ::: "memory")
#define TEAM_SYNC(team) asm volatile("bar.sync %0, 256;" :: "r"((team) + 1) : "memory")

// ---------------- fully fused conv1+conv2+conv3 + inlined compose ---------------
#define SAS 40
#define SM_B   1024
#define SB_MAT 2560
#define A2T(team) (93184u + (uint32_t)(team) * 40960u)
#define A3T(team) (175104u + (uint32_t)(team) * 12800u)
#define C3T(team) (200704u + (uint32_t)(team) * 4752u)
#define XBT(team, buf) (210240u + (uint32_t)(team) * 6272u + (uint32_t)(buf) * 3136u)
#define SM_W1S 222784u
#define SM_B1S 223936u
#define SM_TOTAL 224064
// compose staging (pre-prologue scratch inside [93184, 224064))
#define CPS_E3 93184
#define CPS_C1 98304
#define CPS_E2 103424
#define CPS_W1 168960
#define CPS_EB 187392

__device__ __forceinline__ void prefetch_x(uint32_t sb, uint32_t xoff,
                                           const float* __restrict__ x, int img, int ttid) {
    if (ttid < 196) {
        uint32_t dst = sb + xoff + (uint32_t)ttid * 16u;
        const char* src = (const char*)(x + (size_t)img * 784) + ttid * 16;
        asm volatile("cp.async.ca.shared.global [%0], [%1], 16;" :: "r"(dst), "l"(src));
    }
}

__device__ __forceinline__ void zero_pads(char* smem, uint32_t bufbase, int ttid) {
    for (int z = ttid; z < 600; z += 256) {
        int si = z / 300, r = z - si * 300;
        int ri = r / 5, q = r - ri * 5;
        int row;
        if (ri < 17) row = ri;
        else if (ri < 43) { int k = ri - 17; row = (k >> 1) * 16 + 31 + (k & 1); }
        else row = 239 + (ri - 43);
        *(float4*)(smem + bufbase + si * 20480 + row * 80 + q * 16) =
            make_float4(0.f, 0.f, 0.f, 0.f);
    }
}

__device__ void conv1_compute(char* smem, uint32_t xoff, uint32_t a2b, int ttid) {
    const float* xs = (const float*)(smem + xoff);
    const float* w1s = (const float*)(smem + SM_W1S);
    const float* b1s = (const float*)(smem + SM_B1S);
    for (int u = ttid; u < 784; u += 256) {
        int pos = u >> 2, ocg = u & 3;
        int ph = pos / 14, pw = pos - ph * 14;
        float p[4][4];
#pragma unroll
        for (int r = 0; r < 4; r++) {
            int ir = 2 * ph - 1 + r;
#pragma unroll
            for (int c = 0; c < 4; c++) {
                int icx = 2 * pw - 1 + c;
                p[r][c] = (ir >= 0 && ir < 28 && icx >= 0 && icx < 28) ? xs[ir * 28 + icx] : 0.f;
            }
        }
        uint32_t rowoff = (uint32_t)((((ph + 1) * 16) + pw + 1) * SAS) * 2;
#pragma unroll 2
        for (int o8 = 0; o8 < 8; o8++) {
            int oc = ocg * 8 + o8;
            const float* w = w1s + oc * 9;
            float a0 = 0.f, a1 = 0.f, a2 = 0.f, a3 = 0.f;
#pragma unroll
            for (int kh = 0; kh < 3; kh++)
#pragma unroll
                for (int kw = 0; kw < 3; kw++) {
                    float wv = w[kh * 3 + kw];
                    a0 += p[kh][kw] * wv;     a1 += p[kh][kw + 1] * wv;
                    a2 += p[kh + 1][kw] * wv; a3 += p[kh + 1][kw + 1] * wv;
                }
            float v = fmaxf(fmaxf(fmaxf(a0, a1), fmaxf(a2, a3)) + b1s[oc], 0.f);
            uint32_t off = rowoff + (uint32_t)oc * 2u;
            split_store(smem, a2b + off, a2b + 20480u + off, v);
        }
    }
}

// compose work for blocks 0..23: action a = blk/8, slice s = blk%8 (36 rows)
__device__ void compose_part(char* smem, int tid,
                             const float* __restrict__ ew1, const float* __restrict__ eb1,
                             const float* __restrict__ ew2, const float* __restrict__ eb2,
                             const float* __restrict__ ew3, const float* __restrict__ eb3) {
    int a = blockIdx.x >> 3, s = blockIdx.x & 7;
    float* E3s = (float*)(smem + CPS_E3);
    float* C1s = (float*)(smem + CPS_C1);
    float* E2s = (float*)(smem + CPS_E2);
    float* W1s = (float*)(smem + CPS_W1);
    float* EBs = (float*)(smem + CPS_EB);

    for (int i = tid; i < 1280; i += 512) E3s[i] = ew3[a * 1280 + i];
    {
        const float4* src = (const float4*)(ew2 + a * 16384);
        float4* dst = (float4*)E2s;
        for (int i = tid; i < 4096; i += 512) dst[i] = src[i];
    }
    {
        const float4* src = (const float4*)(ew1 + a * 36864 + s * 4608);
        float4* dst = (float4*)W1s;
        for (int i = tid; i < 1152; i += 512) dst[i] = src[i];
    }
    if (tid < 128) {
        EBs[tid] = eb1[a * 128 + tid];
        EBs[128 + tid] = eb2[a * 128 + tid];
    }
    __syncthreads();
    // C1s = E2 @ E3   (128 rows; staggered j to dodge 128-stride conflicts)
    if (tid < 128) {
        float sc[10];
#pragma unroll
        for (int o = 0; o < 10; o++) sc[o] = 0.f;
        const float* e2r = E2s + tid * 128;
#pragma unroll 4
        for (int jj = 0; jj < 128; jj++) {
            int j = (jj + tid) & 127;
            float e = e2r[j];
#pragma unroll
            for (int o = 0; o < 10; o++) sc[o] += e * E3s[j * 10 + o];
        }
#pragma unroll
        for (int o = 0; o < 10; o++) C1s[tid * 10 + o] = sc[o];
    }
    __syncthreads();
    if (s == 0 && tid < 10) {
        float bb = eb3[a * 10 + tid];
#pragma unroll 4
        for (int i = 0; i < 128; i++) {
            bb += EBs[128 + i] * E3s[i * 10 + tid];
            bb += EBs[i] * C1s[i * 10 + tid];
        }
        g_bc[a * 10 + tid] = bb;
    }
    // Wc slice: 36 rows x 10 outputs, one (k,o) per thread
    if (tid < 360) {
        int kr = tid / 10, o = tid - kr * 10;
        float sc = 0.f;
        const float* e1r = W1s + kr * 128;
#pragma unroll 4
        for (int ii = 0; ii < 128; ii++) {
            int i = (ii + kr) & 127;
            sc += e1r[i] * C1s[i * 10 + o];
        }
        g_Wc[(a * 288 + s * 36 + kr) * 10 + o] = sc;
    }
}

__global__ void __launch_bounds__(512, 1) conv123_kernel(
    const float* __restrict__ x,
    const float* __restrict__ cw1, const float* __restrict__ cb1,
    const float* __restrict__ cw2, const float* __restrict__ cb2,
    const float* __restrict__ cw3, const float* __restrict__ cb3,
    const float* __restrict__ ew1, const float* __restrict__ eb1,
    const float* __restrict__ ew2, const float* __restrict__ eb2,
    const float* __restrict__ ew3, const float* __restrict__ eb3) {
    extern __shared__ char smem[];
    uint32_t sb = smem_u32(smem);
    int tid = threadIdx.x;
    int team = tid >> 8, ttid = tid & 255;
    int wid = ttid >> 5, lane = tid & 31;
    float* ssum = (float*)(smem + 64);
    float* ssq  = (float*)(smem + 192);
    uint32_t a2b = A2T(team), a3b = A3T(team), c3b = C3T(team);
    float* C3 = (float*)(smem + c3b);
    int first_img = blockIdx.x + 148 * team;

    if (blockIdx.x == 0 && tid < 64) g_stats[tid] = 0.f;   // single wave -> safe
    if (blockIdx.x < 24) {
        compose_part(smem, tid, ew1, eb1, ew2, eb2, ew3, eb3);
        __syncthreads();
    }

    if (tid < 32) { ssum[tid] = 0.f; ssq[tid] = 0.f; }
    for (int i = tid; i < 1600; i += 512)
        ((float4*)(smem + A3T(0)))[i] = make_float4(0.f, 0.f, 0.f, 0.f);
    for (int idx = tid; idx < 18432; idx += 512) {
        int conv = idx / 9216, r = idx % 9216;
        int tap = r / 1024, r2 = r % 1024;
        int oc = r2 >> 5, ic = r2 & 31;
        int kh = tap / 3, kw = tap % 3;
        float w = __ldg(&(conv ? cw3 : cw2)[oc * 288 + ic * 9 + kh * 3 + kw]);
        uint32_t bh = SM_B + (uint32_t)((conv * 9 + tap) * 2) * SB_MAT + (oc * SAS + ic) * 2;
        split_store(smem, bh, bh + SB_MAT, w);
    }
    for (int i = tid; i < 288; i += 512) ((float*)(smem + SM_W1S))[i] = cw1[i];
    if (tid < 32) ((float*)(smem + SM_B1S))[tid] = cb1[tid];
    zero_pads(smem, a2b, ttid);
    prefetch_x(sb, XBT(team, 0), x, first_img, ttid);
    CP_COMMIT;
    CP_WAIT0;
    __syncthreads();
    conv1_compute(smem, XBT(team, 0), a2b, ttid);
    if (first_img + 296 < B) prefetch_x(sb, XBT(team, 1), x, first_img + 296, ttid);
    CP_COMMIT;
    TEAM_SYNC(team);

    int g = lane >> 2, tg = lane & 3;
    uint32_t a_r = (uint32_t)(lane & 15), a_c = (uint32_t)((lane >> 4) * 8);
    uint32_t b_row = (uint32_t)(((lane >> 4) << 3) + (lane & 7));
    uint32_t b_c = (uint32_t)((lane & 8) ? 8 : 0);
    float lsum = 0.f, lsq = 0.f, lsum2 = 0.f, lsq2 = 0.f;
    int myoc = ttid / 9, myoc2 = (ttid + 256) / 9;
    int mt[2] = { 2 * wid + 1, 2 * wid + 2 };
    int cv2 = wid < 7;
    int tnum = wid >> 1, np3 = wid & 1;
    float bias0[4], bias1[4];
#pragma unroll
    for (int n = 0; n < 4; n++) {
        bias0[n] = __ldg(&cb2[n * 8 + 2 * tg]);
        bias1[n] = __ldg(&cb2[n * 8 + 2 * tg + 1]);
    }

    for (int it = 0; it < 14; it++) {
        int img = first_img + 296 * it;
        int active = img < B;
        if (cv2) {
            float acc[2][4][4];
#pragma unroll
            for (int t = 0; t < 2; t++)
#pragma unroll
                for (int n = 0; n < 4; n++)
#pragma unroll
                    for (int i = 0; i < 4; i++) acc[t][n][i] = 0.f;
#pragma unroll
            for (int tap = 0; tap < 9; tap++) {
                uint32_t bmat = sb + SM_B + (uint32_t)(tap * 2) * SB_MAT;
                uint32_t Bh[2][2][4], Bl[2][2][4];
#pragma unroll
                for (int np = 0; np < 2; np++)
#pragma unroll
                    for (int j = 0; j < 2; j++) {
                        uint32_t boff = (((uint32_t)np * 16 + b_row) * SAS + (uint32_t)j * 16 + b_c) * 2;
                        LDSM4(Bh[np][j], bmat + boff);
                        LDSM4(Bl[np][j], bmat + SB_MAT + boff);
                    }
                int dr = (tap / 3 - 1) * 16 + (tap % 3 - 1) + 1;
#pragma unroll
                for (int j = 0; j < 2; j++) {
                    uint32_t Ah[2][4], Al[2][4];
#pragma unroll
                    for (int t = 0; t < 2; t++) {
                        uint32_t aoff = (uint32_t)((mt[t] * 16 + dr + (int)a_r) * SAS) * 2
                                        + ((uint32_t)j * 16 + a_c) * 2;
                        LDSM4(Ah[t], sb + a2b + aoff);
                        LDSM4(Al[t], sb + a2b + 20480u + aoff);
                    }
#pragma unroll
                    for (int t = 0; t < 2; t++) {
                        mma_pair(acc[t][0], acc[t][1], Ah[t], Bh[0][j]);
                        mma_pair(acc[t][2], acc[t][3], Ah[t], Bh[1][j]);
                    }
#pragma unroll
                    for (int t = 0; t < 2; t++) {
                        mma_pair(acc[t][0], acc[t][1], Ah[t], Bl[0][j]);
                        mma_pair(acc[t][2], acc[t][3], Ah[t], Bl[1][j]);
                    }
#pragma unroll
                    for (int t = 0; t < 2; t++) {
                        mma_pair(acc[t][0], acc[t][1], Al[t], Bh[0][j]);
                        mma_pair(acc[t][2], acc[t][3], Al[t], Bh[1][j]);
                    }
                }
            }
#pragma unroll
            for (int n = 0; n < 4; n++) {
                float vA0 = fmaxf(acc[0][n][0], acc[1][n][0]);
                float vA1 = fmaxf(acc[0][n][1], acc[1][n][1]);
                float vB0 = fmaxf(acc[0][n][2], acc[1][n][2]);
                float vB1 = fmaxf(acc[0][n][3], acc[1][n][3]);
                float qA0 = fmaxf(vA0, __shfl_xor_sync(0xffffffffu, vA0, 4));
                float qA1 = fmaxf(vA1, __shfl_xor_sync(0xffffffffu, vA1, 4));
                float qB0 = fmaxf(vB0, __shfl_xor_sync(0xffffffffu, vB0, 4));
                float qB1 = fmaxf(vB1, __shfl_xor_sync(0xffffffffu, vB1, 4));
                if ((g & 1) == 0) {
                    int oc0 = n * 8 + 2 * tg;
                    int pcA = g >> 1;
                    uint32_t rowA = (uint32_t)((wid + 2) * 8 + pcA);
                    uint32_t offA = (rowA * SAS + (uint32_t)oc0) * 2;
                    split_store(smem, a3b + offA, a3b + 6400u + offA,
                                fmaxf(qA0 + bias0[n], 0.f));
                    split_store(smem, a3b + offA + 2, a3b + 6400u + offA + 2,
                                fmaxf(qA1 + bias1[n], 0.f));
                    int pcB = (g >> 1) + 4;
                    if (pcB < 7) {
                        uint32_t rowB = (uint32_t)((wid + 2) * 8 + pcB);
                        uint32_t offB = (rowB * SAS + (uint32_t)oc0) * 2;
                        split_store(smem, a3b + offB, a3b + 6400u + offB,
                                    fmaxf(qB0 + bias0[n], 0.f));
                        split_store(smem, a3b + offB + 2, a3b + 6400u + offB + 2,
                                    fmaxf(qB1 + bias1[n], 0.f));
                    }
                }
            }
        }
        TEAM_SYNC(team);
        if (wid < 6) {
            float acc3[2][2][4];
#pragma unroll
            for (int bk = 0; bk < 2; bk++)
#pragma unroll
                for (int n = 0; n < 2; n++)
#pragma unroll
                    for (int i = 0; i < 4; i++) acc3[bk][n][i] = 0.f;
            int base = 16 + tnum * 16;
#pragma unroll
            for (int tap = 0; tap < 9; tap++) {
                uint32_t bmat = sb + SM_B + (uint32_t)(18 + tap * 2) * SB_MAT;
                uint32_t B3h[2][4], B3l[2][4];
#pragma unroll
                for (int j = 0; j < 2; j++) {
                    uint32_t boff = (((uint32_t)np3 * 16 + b_row) * SAS + (uint32_t)j * 16 + b_c) * 2;
                    LDSM4(B3h[j], bmat + boff);
                    LDSM4(B3l[j], bmat + SB_MAT + boff);
                }
                int dr3 = (tap / 3 - 1) * 8 + (tap % 3 - 1);
#pragma unroll
                for (int j = 0; j < 2; j++) {
                    uint32_t aoff = (uint32_t)((base + dr3 + (int)a_r) * SAS) * 2
                                    + ((uint32_t)j * 16 + a_c) * 2;
                    uint32_t A3h[4], A3l[4];
                    LDSM4(A3h, sb + a3b + aoff);
                    LDSM4(A3l, sb + a3b + 6400u + aoff);
                    mma_pair(acc3[j][0], acc3[j][1], A3h, B3h[j]);
                    mma_pair(acc3[j ^ 1][0], acc3[j ^ 1][1], A3h, B3l[j]);
                    mma_pair(acc3[j][0], acc3[j][1], A3l, B3h[j]);
                }
            }
            if (g < 6) {
#pragma unroll
                for (int n = 0; n < 2; n++) {
                    int col = np3 * 16 + n * 8 + 2 * tg;
                    int pos0 = (2 * tnum) * 6 + g;
                    int pos1 = (2 * tnum + 1) * 6 + g;
                    C3[pos0 * 33 + col] = acc3[0][n][0] + acc3[1][n][0];
                    C3[pos0 * 33 + col + 1] = acc3[0][n][1] + acc3[1][n][1];
                    C3[pos1 * 33 + col] = acc3[0][n][2] + acc3[1][n][2];
                    C3[pos1 * 33 + col + 1] = acc3[0][n][3] + acc3[1][n][3];
                }
            }
        }
        CP_WAIT0;
        TEAM_SYNC(team);
        if (active) {
            float* go = g_out3 + img * 288;
            {
                int oc = myoc, pos = ttid - oc * 9;
                int pr = pos / 3, pc = pos - pr * 3;
                const float* c0 = C3 + ((2 * pr) * 6 + 2 * pc) * 33 + oc;
                float v = fmaxf(fmaxf(c0[0], c0[33]), fmaxf(c0[6 * 33], c0[7 * 33]));
                v = fmaxf(v + __ldg(&cb3[oc]), 0.f);
                go[ttid] = v; lsum += v; lsq += v * v;
            }
            if (ttid < 32) {
                int idx = ttid + 256;
                int oc = myoc2, pos = idx - oc * 9;
                int pr = pos / 3, pc = pos - pr * 3;
                const float* c0 = C3 + ((2 * pr) * 6 + 2 * pc) * 33 + oc;
                float v = fmaxf(fmaxf(c0[0], c0[33]), fmaxf(c0[6 * 33], c0[7 * 33]));
                v = fmaxf(v + __ldg(&cb3[oc]), 0.f);
                go[idx] = v; lsum2 += v; lsq2 += v * v;
            }
        }
        {
            int imgN = img + 296;
            if (it < 13 && imgN < B)
                conv1_compute(smem, XBT(team, (it + 1) & 1), a2b, ttid);
            int imgP = img + 592;
            if (it < 12 && imgP < B)
                prefetch_x(sb, XBT(team, it & 1), x, imgP, ttid);
        }
        CP_COMMIT;
        TEAM_SYNC(team);
    }
    atomicAdd(&ssum[myoc], lsum); atomicAdd(&ssq[myoc], lsq);
    if (ttid < 32) { atomicAdd(&ssum[myoc2], lsum2); atomicAdd(&ssq[myoc2], lsq2); }
    __syncthreads();
    if (tid < 32) {
        atomicAdd(&g_stats[tid], ssum[tid]);
        atomicAdd(&g_stats[32 + tid], ssq[tid]);
    }
}

// ---------------- MLP: smem-staged weights, double-buffered cp.async ------------
#define MS_SCALE 0
#define MS_YS    256
#define MS_HA    18688
#define MS_HB    26880
#define MS_WBUF  35072
#define MLP_SMEM 67840

__device__ __forceinline__ void mlp_prefetch(uint32_t sb, int ti,
                                             const float* __restrict__ pw1,
                                             const float* __restrict__ pw2, int tid) {
    const char* src = (const char*)((ti < 9) ? (pw1 + ti * 4096) : (pw2 + (ti - 9) * 4096));
    uint32_t dst = sb + MS_WBUF + (uint32_t)(ti & 1) * 16384u;
#pragma unroll
    for (int c = 0; c < 4; c++) {
        int i = tid + c * 256;
        asm volatile("cp.async.ca.shared.global [%0], [%1], 16;"
                     :: "r"(dst + (uint32_t)i * 16u), "l"(src + i * 16) : "memory");
    }
}

__global__ void __launch_bounds__(256) mlp_kernel(
    const float* __restrict__ pw1, const float* __restrict__ pb1,
    const float* __restrict__ pw2, const float* __restrict__ pb2,
    const float* __restrict__ pw3, const float* __restrict__ pb3,
    const float* __restrict__ bn_g, const float* __restrict__ bn_b,
    float* __restrict__ out, int write_actions) {
    extern __shared__ char ms[];
    uint32_t sb = smem_u32(ms);
    float* s_scale = (float*)(ms + MS_SCALE);
    float* s_shift = s_scale + 32;
    float* ys = (float*)(ms + MS_YS);
    float* ha = (float*)(ms + MS_HA);
    float* hb = (float*)(ms + MS_HB);
    int tid = threadIdx.x;
    int w = tid >> 5, lane = tid & 31;
    int e0 = blockIdx.x * 16;

    mlp_prefetch(sb, 0, pw1, pw2, tid); CP_COMMIT;
    mlp_prefetch(sb, 1, pw1, pw2, tid); CP_COMMIT;

    if (tid < 32) {
        const float inv_n = 1.0f / (float)(B * 9);
        float m = g_stats[tid] * inv_n;
        float var = g_stats[32 + tid] * inv_n - m * m;
        float sc = bn_g[tid] * rsqrtf(var + 1e-5f);
        s_scale[tid] = sc;
        s_shift[tid] = bn_b[tid] - m * sc;
    }
    __syncthreads();
    for (int idx = tid; idx < 4608; idx += 256) {
        int e = idx / 288, k = idx - e * 288, c = k / 9;
        ys[idx] = g_out3[(e0 + e) * 288 + k] * s_scale[c] + s_shift[c];
    }

    const float* y0p = ys + (2 * w) * 288;
    const float* y1p = ys + (2 * w + 1) * 288;
    float acc1[2][4], acc2[2][4];
    {
        float4 bv = *(const float4*)(pb1 + lane * 4);
        acc1[0][0] = bv.x; acc1[0][1] = bv.y; acc1[0][2] = bv.z; acc1[0][3] = bv.w;
        acc1[1][0] = bv.x; acc1[1][1] = bv.y; acc1[1][2] = bv.z; acc1[1][3] = bv.w;
        float4 bv2 = *(const float4*)(pb2 + lane * 4);
        acc2[0][0] = bv2.x; acc2[0][1] = bv2.y; acc2[0][2] = bv2.z; acc2[0][3] = bv2.w;
        acc2[1][0] = bv2.x; acc2[1][1] = bv2.y; acc2[1][2] = bv2.z; acc2[1][3] = bv2.w;
    }

    for (int ti = 0; ti < 13; ti++) {
        if (ti < 12) { CP_WAIT1; } else { CP_WAIT0; }
        __syncthreads();
        const float4* wt = (const float4*)(ms + MS_WBUF + (uint32_t)(ti & 1) * 16384u);
        if (ti < 9) {
            int kb = ti * 32;
#pragma unroll 8
            for (int kl = 0; kl < 32; kl++) {
                float4 w4 = wt[kl * 32 + lane];
                float y0 = y0p[kb + kl], y1 = y1p[kb + kl];
                acc1[0][0] += y0 * w4.x; acc1[0][1] += y0 * w4.y;
                acc1[0][2] += y0 * w4.z; acc1[0][3] += y0 * w4.w;
                acc1[1][0] += y1 * w4.x; acc1[1][1] += y1 * w4.y;
                acc1[1][2] += y1 * w4.z; acc1[1][3] += y1 * w4.w;
            }
            if (ti == 8) {
#pragma unroll
                for (int e = 0; e < 2; e++)
                    *(float4*)(ha + (2 * w + e) * 128 + lane * 4) =
                        make_float4(fmaxf(acc1[e][0], 0.f), fmaxf(acc1[e][1], 0.f),
                                    fmaxf(acc1[e][2], 0.f), fmaxf(acc1[e][3], 0.f));
            }
        } else {
            int kb = (ti - 9) * 32;
            const float* h0 = ha + (2 * w) * 128;
            const float* h1 = ha + (2 * w + 1) * 128;
#pragma unroll 8
            for (int kl = 0; kl < 32; kl++) {
                float4 w4 = wt[kl * 32 + lane];
                float y0 = h0[kb + kl], y1 = h1[kb + kl];
                acc2[0][0] += y0 * w4.x; acc2[0][1] += y0 * w4.y;
                acc2[0][2] += y0 * w4.z; acc2[0][3] += y0 * w4.w;
                acc2[1][0] += y1 * w4.x; acc2[1][1] += y1 * w4.y;
                acc2[1][2] += y1 * w4.z; acc2[1][3] += y1 * w4.w;
            }
        }
        __syncthreads();
        if (ti + 2 < 13) { mlp_prefetch(sb, ti + 2, pw1, pw2, tid); CP_COMMIT; }
    }
#pragma unroll
    for (int e = 0; e < 2; e++)
        *(float4*)(hb + (2 * w + e) * 128 + lane * 4) =
            make_float4(fmaxf(acc2[e][0], 0.f), fmaxf(acc2[e][1], 0.f),
                        fmaxf(acc2[e][2], 0.f), fmaxf(acc2[e][3], 0.f));
    __syncwarp();

    for (int e = 0; e < 2; e++) {
        int le = 2 * w + e;
        float p0 = 0.f, p1 = 0.f, p2 = 0.f;
#pragma unroll
        for (int kk = 0; kk < 4; kk++) {
            int k = lane + 32 * kk;
            float hv = hb[le * 128 + k];
            const float* wr = pw3 + k * 3;
            p0 += hv * wr[0]; p1 += hv * wr[1]; p2 += hv * wr[2];
        }
#pragma unroll
        for (int off = 16; off > 0; off >>= 1) {
            p0 += __shfl_down_sync(0xffffffffu, p0, off);
            p1 += __shfl_down_sync(0xffffffffu, p1, off);
            p2 += __shfl_down_sync(0xffffffffu, p2, off);
        }
        int a = 0;
        if (lane == 0) {
            p0 += __ldg(&pb3[0]); p1 += __ldg(&pb3[1]); p2 += __ldg(&pb3[2]);
            float best = p0;
            if (p1 > best) { best = p1; a = 1; }
            if (p2 > best) { a = 2; }
        }
        a = __shfl_sync(0xffffffffu, a, 0);
        float po[10];
#pragma unroll
        for (int o = 0; o < 10; o++) po[o] = 0.f;
        const float* Wb = g_Wc + a * 2880;
        const float* ye = ys + le * 288;
#pragma unroll
        for (int kk = 0; kk < 9; kk++) {
            int k = lane + 32 * kk;
            float yv = ye[k];
            const float* wr = Wb + k * 10;
#pragma unroll
            for (int o = 0; o < 10; o++) po[o] += yv * wr[o];
        }
#pragma unroll
        for (int off = 16; off > 0; off >>= 1) {
#pragma unroll
            for (int o = 0; o < 10; o++) po[o] += __shfl_down_sync(0xffffffffu, po[o], off);
        }
        if (lane == 0) {
            int gg = e0 + le;
#pragma unroll
            for (int o = 0; o < 10; o++) out[gg * 10 + o] = po[o] + g_bc[a * 10 + o];
            if (write_actions) out[B * 10 + gg] = (float)a;
        }
    }
}

// ---------------- launch --------------------------------------------------------
extern "C" void kernel_launch(void* const* d_in, const int* in_sizes, int n_in,
                              void* d_out, int out_size) {
    const float* x    = (const float*)d_in[0];
    const float* cw1  = (const float*)d_in[1];
    const float* cb1  = (const float*)d_in[2];
    const float* cw2  = (const float*)d_in[3];
    const float* cb2  = (const float*)d_in[4];
    const float* cw3  = (const float*)d_in[5];
    const float* cb3  = (const float*)d_in[6];
    const float* bn_g = (const float*)d_in[7];
    const float* bn_b = (const float*)d_in[8];
    const float* pw1  = (const float*)d_in[9];
    const float* pb1  = (const float*)d_in[10];
    const float* pw2  = (const float*)d_in[11];
    const float* pb2  = (const float*)d_in[12];
    const float* pw3  = (const float*)d_in[13];
    const float* pb3  = (const float*)d_in[14];
    const float* ew1  = (const float*)d_in[15];
    const float* eb1  = (const float*)d_in[16];
    const float* ew2  = (const float*)d_in[17];
    const float* eb2  = (const float*)d_in[18];
    const float* ew3  = (const float*)d_in[19];
    const float* eb3  = (const float*)d_in[20];
    float* out = (float*)d_out;
    int write_actions = (out_size >= B * 10 + B) ? 1 : 0;

    cudaFuncSetAttribute(conv123_kernel, cudaFuncAttributeMaxDynamicSharedMemorySize, SM_TOTAL);
    cudaFuncSetAttribute(mlp_kernel, cudaFuncAttributeMaxDynamicSharedMemorySize, MLP_SMEM);

    conv123_kernel<<<148, 512, SM_TOTAL>>>(x, cw1, cb1, cw2, cb2, cw3, cb3,
                                           ew1, eb1, ew2, eb2, ew3, eb3);     // 1 (compose inlined)
    mlp_kernel<<<B / 16, 256, MLP_SMEM>>>(pw1, pb1, pw2, pb2, pw3, pb3,
                                          bn_g, bn_b, out, write_actions);    // 2
}